// round 1
// baseline (speedup 1.0000x reference)
#include <cuda_runtime.h>
#include <math.h>

// Problem constants
#define NB   16          // batch
#define NN   8192        // nodes
#define DHH  64          // hidden / input dim
#define DCAT 128         // concat dim (input + hidden)
#define BD   (NB * DCAT) // 2048 : width of feature matrices in (N, B*DCAT) layout

// -------- scratch (device globals; allocation-free rule) --------
__device__ float g_X [(size_t)NN * BD];            // features (N, B*128)  == (N*B, 128) row-major
__device__ float g_T1[(size_t)NN * BD];
__device__ float g_T2[(size_t)NN * BD];
__device__ float g_PRE[(size_t)NN * NB * DCAT];    // preactivation (N*B, 128) or (N*B, 64)
__device__ float g_U [(size_t)NN * NB * DHH];      // update gate u, (N, B, 64)

// ============================ GEMM ============================
// C[M,Nc] = alpha * A[M,K] @ B[K,Nc] + beta * D[M,Nc] + bias[Nc]
// Requirements (all satisfied by our shapes): M % 128 == 0, K % 16 == 0,
// Nc % 4 == 0, lda/ldb/ldc/ldd % 4 == 0, 16B-aligned bases.
#define BMT 128
#define BNT 128
#define BKT 16
#define TM  8
#define TN  8

__global__ __launch_bounds__(256, 2)
void gemm_kernel(int M, int Nc, int K,
                 const float* __restrict__ A, int lda,
                 const float* __restrict__ B, int ldb,
                 float* __restrict__ C, int ldc,
                 const float* __restrict__ D, int ldd,
                 float alpha, float beta,
                 const float* __restrict__ bias)
{
    __shared__ __align__(16) float As[2][BKT][BMT + 4];
    __shared__ __align__(16) float Bs[2][BKT][BNT];

    const int tid = threadIdx.x;
    const int tx = tid & 15;
    const int ty = tid >> 4;
    const int bm = blockIdx.y * BMT;
    const int bn = blockIdx.x * BNT;

    // loader mapping
    const int arow = tid >> 2;          // 0..63 (2 iters -> 128 rows)
    const int acol = (tid & 3) << 2;    // 0,4,8,12
    const int brow = tid >> 5;          // 0..7  (2 iters -> 16 rows)
    const int bcol = (tid & 31) << 2;   // 0..124

    float acc[TM][TN];
#pragma unroll
    for (int i = 0; i < TM; i++)
#pragma unroll
        for (int j = 0; j < TN; j++) acc[i][j] = 0.f;

    float4 pa0, pa1, pb0, pb1;

    // ---- initial tile (kt = 0) ----
    {
        const float* Ab = A + (size_t)(bm + arow) * lda + acol;
        pa0 = *(const float4*)Ab;
        pa1 = *(const float4*)(Ab + (size_t)64 * lda);
        const int c0 = bn + bcol;
        if (c0 < Nc) {
            const float* Bb = B + (size_t)brow * ldb + c0;
            pb0 = *(const float4*)Bb;
            pb1 = *(const float4*)(Bb + (size_t)8 * ldb);
        } else {
            pb0 = make_float4(0.f, 0.f, 0.f, 0.f);
            pb1 = pb0;
        }
        As[0][acol + 0][arow]      = pa0.x;
        As[0][acol + 1][arow]      = pa0.y;
        As[0][acol + 2][arow]      = pa0.z;
        As[0][acol + 3][arow]      = pa0.w;
        As[0][acol + 0][arow + 64] = pa1.x;
        As[0][acol + 1][arow + 64] = pa1.y;
        As[0][acol + 2][arow + 64] = pa1.z;
        As[0][acol + 3][arow + 64] = pa1.w;
        *(float4*)&Bs[0][brow][bcol]     = pb0;
        *(float4*)&Bs[0][brow + 8][bcol] = pb1;
    }
    __syncthreads();

    int buf = 0;
    for (int kt = 0; kt < K; kt += BKT) {
        const bool has_next = (kt + BKT) < K;
        if (has_next) {
            const int kn = kt + BKT;
            const float* Ab = A + (size_t)(bm + arow) * lda + kn + acol;
            pa0 = *(const float4*)Ab;
            pa1 = *(const float4*)(Ab + (size_t)64 * lda);
            const int c0 = bn + bcol;
            if (c0 < Nc) {
                const float* Bb = B + (size_t)(kn + brow) * ldb + c0;
                pb0 = *(const float4*)Bb;
                pb1 = *(const float4*)(Bb + (size_t)8 * ldb);
            } else {
                pb0 = make_float4(0.f, 0.f, 0.f, 0.f);
                pb1 = pb0;
            }
        }

#pragma unroll
        for (int k = 0; k < BKT; ++k) {
            float rA[TM], rB[TN];
            *(float4*)&rA[0] = *(const float4*)&As[buf][k][ty * TM];
            *(float4*)&rA[4] = *(const float4*)&As[buf][k][ty * TM + 4];
            *(float4*)&rB[0] = *(const float4*)&Bs[buf][k][tx * TN];
            *(float4*)&rB[4] = *(const float4*)&Bs[buf][k][tx * TN + 4];
#pragma unroll
            for (int i = 0; i < TM; i++)
#pragma unroll
                for (int j = 0; j < TN; j++)
                    acc[i][j] = fmaf(rA[i], rB[j], acc[i][j]);
        }

        if (has_next) {
            buf ^= 1;
            As[buf][acol + 0][arow]      = pa0.x;
            As[buf][acol + 1][arow]      = pa0.y;
            As[buf][acol + 2][arow]      = pa0.z;
            As[buf][acol + 3][arow]      = pa0.w;
            As[buf][acol + 0][arow + 64] = pa1.x;
            As[buf][acol + 1][arow + 64] = pa1.y;
            As[buf][acol + 2][arow + 64] = pa1.z;
            As[buf][acol + 3][arow + 64] = pa1.w;
            *(float4*)&Bs[buf][brow][bcol]     = pb0;
            *(float4*)&Bs[buf][brow + 8][bcol] = pb1;
            __syncthreads();
        }
    }

    // ---- epilogue ----
#pragma unroll
    for (int i = 0; i < TM; i++) {
        const int row = bm + ty * TM + i;
#pragma unroll
        for (int j = 0; j < TN; j += 4) {
            const int col = bn + tx * TN + j;
            if (col < Nc) {
                float4 v;
                v.x = alpha * acc[i][j + 0];
                v.y = alpha * acc[i][j + 1];
                v.z = alpha * acc[i][j + 2];
                v.w = alpha * acc[i][j + 3];
                if (beta != 0.f) {
                    const float4 dv = *(const float4*)&D[(size_t)row * ldd + col];
                    v.x += beta * dv.x; v.y += beta * dv.y;
                    v.z += beta * dv.z; v.w += beta * dv.w;
                }
                if (bias) {
                    const float4 bv = *(const float4*)&bias[col];
                    v.x += bv.x; v.y += bv.y; v.z += bv.z; v.w += bv.w;
                }
                *(float4*)&C[(size_t)row * ldc + col] = v;
            }
        }
    }
}

// ============================ elementwise ============================

__device__ __forceinline__ float sigmoidf_(float x) {
    return 1.f / (1.f + expf(-x));
}

// X[n][b*128 + d] = d<64 ? inputs[b][n][d] : states[b][n][d-64]
__global__ void build_x_kernel(const float* __restrict__ inputs,
                               const float* __restrict__ states,
                               float* __restrict__ X)
{
    int idx = blockIdx.x * blockDim.x + threadIdx.x;
    if (idx >= NN * BD) return;
    const int n = idx / BD;
    const int r = idx - n * BD;
    const int b = r >> 7;         // / 128
    const int d = r & 127;
    float v;
    if (d < DHH) v = inputs[((size_t)b * NN + n) * DHH + d];
    else         v = states[((size_t)b * NN + n) * DHH + (d - DHH)];
    X[idx] = v;
}

// From PRE (ru preact, (N*B,128)): r=sigmoid(:64), u=sigmoid(64:)
// store u; rebuild X as xc = [inputs, r*states]
__global__ void gate_kernel(const float* __restrict__ inputs,
                            const float* __restrict__ states,
                            const float* __restrict__ PRE,
                            float* __restrict__ X,
                            float* __restrict__ U)
{
    int idx = blockIdx.x * blockDim.x + threadIdx.x;
    if (idx >= NN * NB * DHH) return;
    const int n = idx / (NB * DHH);
    const int r0 = idx - n * (NB * DHH);
    const int b = r0 >> 6;        // / 64
    const int d = r0 & 63;
    const size_t prow = (size_t)(n * NB + b) * DCAT;
    const float rr = sigmoidf_(PRE[prow + d]);
    const float uu = sigmoidf_(PRE[prow + DHH + d]);
    U[idx] = uu;
    const float st = states[((size_t)b * NN + n) * DHH + d];
    const size_t xb = (size_t)n * BD + (size_t)b * DCAT;
    X[xb + d]       = inputs[((size_t)b * NN + n) * DHH + d];
    X[xb + DHH + d] = rr * st;
}

// new_state = u*states + (1-u)*tanh(prec); written in (B,N,64), twice if room
__global__ void final_kernel(const float* __restrict__ states,
                             const float* __restrict__ PREC,
                             const float* __restrict__ U,
                             float* __restrict__ out,
                             int out_size)
{
    int idx = blockIdx.x * blockDim.x + threadIdx.x;
    if (idx >= NN * NB * DHH) return;
    const int n = idx / (NB * DHH);
    const int r0 = idx - n * (NB * DHH);
    const int b = r0 >> 6;
    const int d = r0 & 63;
    const float uu = U[idx];
    const float cc = tanhf(PREC[(size_t)(n * NB + b) * DHH + d]);
    const float st = states[((size_t)b * NN + n) * DHH + d];
    const float ns = uu * st + (1.f - uu) * cc;
    const size_t o = ((size_t)b * NN + n) * DHH + d;
    out[o] = ns;
    const size_t total = (size_t)NB * NN * DHH;
    if ((size_t)out_size >= 2 * total) out[total + o] = ns;
}

// ============================ launch ============================

extern "C" void kernel_launch(void* const* d_in, const int* in_sizes, int n_in,
                              void* d_out, int out_size)
{
    const float* inputs   = (const float*)d_in[0];
    const float* states   = (const float*)d_in[1];
    const float* supports = (const float*)d_in[2];
    const float* W_ru     = (const float*)d_in[3];
    const float* b_ru     = (const float*)d_in[4];
    const float* W_c      = (const float*)d_in[5];
    const float* b_c      = (const float*)d_in[6];
    float* out = (float*)d_out;

    float *pX, *pT1, *pT2, *pPRE, *pU;
    cudaGetSymbolAddress((void**)&pX,   g_X);
    cudaGetSymbolAddress((void**)&pT1,  g_T1);
    cudaGetSymbolAddress((void**)&pT2,  g_T2);
    cudaGetSymbolAddress((void**)&pPRE, g_PRE);
    cudaGetSymbolAddress((void**)&pU,   g_U);

    const float* S0 = supports;
    const float* S1 = supports + (size_t)NN * NN;

    const dim3 blk(256);
    const dim3 gBig(BD / BNT, NN / BMT);          // (16, 64) : S @ X gemms
    const dim3 gProj(1, (NN * NB) / BMT);         // (1, 1024): feature @ W gemms
    const int MP = NN * NB;                       // 131072

    // ---------- build x = [inputs, states] ----------
    build_x_kernel<<<(NN * BD + 255) / 256, blk>>>(inputs, states, pX);

    // ---------- ru pre-activation ----------
    // PRE = X @ Wru[0:128] + b_ru
    gemm_kernel<<<gProj, blk>>>(MP, 2 * DHH, DCAT, pX, DCAT,
                                W_ru + 0 * DCAT * 2 * DHH, 2 * DHH,
                                pPRE, 2 * DHH, (const float*)0, 0, 1.f, 0.f, b_ru);
    // T1 = S0 @ X
    gemm_kernel<<<gBig, blk>>>(NN, BD, NN, S0, NN, pX, BD, pT1, BD,
                               (const float*)0, 0, 1.f, 0.f, (const float*)0);
    gemm_kernel<<<gProj, blk>>>(MP, 2 * DHH, DCAT, pT1, DCAT,
                                W_ru + 1 * DCAT * 2 * DHH, 2 * DHH,
                                pPRE, 2 * DHH, pPRE, 2 * DHH, 1.f, 1.f, (const float*)0);
    // T2 = 2*S0@T1 - X
    gemm_kernel<<<gBig, blk>>>(NN, BD, NN, S0, NN, pT1, BD, pT2, BD,
                               pX, BD, 2.f, -1.f, (const float*)0);
    gemm_kernel<<<gProj, blk>>>(MP, 2 * DHH, DCAT, pT2, DCAT,
                                W_ru + 2 * DCAT * 2 * DHH, 2 * DHH,
                                pPRE, 2 * DHH, pPRE, 2 * DHH, 1.f, 1.f, (const float*)0);
    // T1 = S1 @ X
    gemm_kernel<<<gBig, blk>>>(NN, BD, NN, S1, NN, pX, BD, pT1, BD,
                               (const float*)0, 0, 1.f, 0.f, (const float*)0);
    gemm_kernel<<<gProj, blk>>>(MP, 2 * DHH, DCAT, pT1, DCAT,
                                W_ru + 3 * DCAT * 2 * DHH, 2 * DHH,
                                pPRE, 2 * DHH, pPRE, 2 * DHH, 1.f, 1.f, (const float*)0);
    // T2 = 2*S1@T1 - X
    gemm_kernel<<<gBig, blk>>>(NN, BD, NN, S1, NN, pT1, BD, pT2, BD,
                               pX, BD, 2.f, -1.f, (const float*)0);
    gemm_kernel<<<gProj, blk>>>(MP, 2 * DHH, DCAT, pT2, DCAT,
                                W_ru + 4 * DCAT * 2 * DHH, 2 * DHH,
                                pPRE, 2 * DHH, pPRE, 2 * DHH, 1.f, 1.f, (const float*)0);

    // ---------- gates: u, and xc = [inputs, r*states] into X ----------
    gate_kernel<<<(NN * NB * DHH + 255) / 256, blk>>>(inputs, states, pPRE, pX, pU);

    // ---------- c pre-activation (width 64) ----------
    gemm_kernel<<<gProj, blk>>>(MP, DHH, DCAT, pX, DCAT,
                                W_c + 0 * DCAT * DHH, DHH,
                                pPRE, DHH, (const float*)0, 0, 1.f, 0.f, b_c);
    gemm_kernel<<<gBig, blk>>>(NN, BD, NN, S0, NN, pX, BD, pT1, BD,
                               (const float*)0, 0, 1.f, 0.f, (const float*)0);
    gemm_kernel<<<gProj, blk>>>(MP, DHH, DCAT, pT1, DCAT,
                                W_c + 1 * DCAT * DHH, DHH,
                                pPRE, DHH, pPRE, DHH, 1.f, 1.f, (const float*)0);
    gemm_kernel<<<gBig, blk>>>(NN, BD, NN, S0, NN, pT1, BD, pT2, BD,
                               pX, BD, 2.f, -1.f, (const float*)0);
    gemm_kernel<<<gProj, blk>>>(MP, DHH, DCAT, pT2, DCAT,
                                W_c + 2 * DCAT * DHH, DHH,
                                pPRE, DHH, pPRE, DHH, 1.f, 1.f, (const float*)0);
    gemm_kernel<<<gBig, blk>>>(NN, BD, NN, S1, NN, pX, BD, pT1, BD,
                               (const float*)0, 0, 1.f, 0.f, (const float*)0);
    gemm_kernel<<<gProj, blk>>>(MP, DHH, DCAT, pT1, DCAT,
                                W_c + 3 * DCAT * DHH, DHH,
                                pPRE, DHH, pPRE, DHH, 1.f, 1.f, (const float*)0);
    gemm_kernel<<<gBig, blk>>>(NN, BD, NN, S1, NN, pT1, BD, pT2, BD,
                               pX, BD, 2.f, -1.f, (const float*)0);
    gemm_kernel<<<gProj, blk>>>(MP, DHH, DCAT, pT2, DCAT,
                                W_c + 4 * DCAT * DHH, DHH,
                                pPRE, DHH, pPRE, DHH, 1.f, 1.f, (const float*)0);

    // ---------- final state ----------
    final_kernel<<<(NN * NB * DHH + 255) / 256, blk>>>(states, pPRE, pU, out, out_size);
}

// round 3
// speedup vs baseline: 3.1430x; 3.1430x over previous
#include <cuda_runtime.h>
#include <math.h>
#include <stdint.h>

// Problem constants
#define NB   16          // batch
#define NN   8192        // nodes
#define DHH  64          // hidden / input dim
#define DCAT 128         // concat dim (input + hidden)
#define BD   (NB * DCAT) // 2048 : width of feature matrices in (N, B*DCAT) layout

// -------- scratch (device globals; allocation-free rule) --------
__device__ float g_X [(size_t)NN * BD];
__device__ float g_T1[(size_t)NN * BD];
__device__ float g_T2[(size_t)NN * BD];
__device__ float g_PRE[(size_t)NN * NB * DCAT];
__device__ float g_U [(size_t)NN * NB * DHH];

// ---------------- cp.async helpers (note ": :" not "::") ----------------
__device__ __forceinline__ void cp_async16(uint32_t dst, const float* src) {
    asm volatile("cp.async.cg.shared.global [%0], [%1], 16;\n"
                 : : "r"(dst), "l"(src) : "memory");
}
__device__ __forceinline__ void cp_commit() {
    asm volatile("cp.async.commit_group;\n" : : : "memory");
}
template <int N>
__device__ __forceinline__ void cp_wait() {
    asm volatile("cp.async.wait_group %0;\n" : : "n"(N) : "memory");
}

// ===================== TF32 tensor-core GEMM =====================
// C[M,Nc] = alpha * A @ B + beta * D  (row-major fp32)
// Block tile 128x128x16, 256 threads, 8 warps (2m x 4n), warp tile 64x32.

#define TBM 128
#define TBN 128
#define TBK 16
#define ASTR 20    // As row stride (floats)
#define BSTR 136   // Bs row stride (floats)

__global__ __launch_bounds__(256, 2)
void tf32_gemm_kernel(const float* __restrict__ A, int lda,
                      const float* __restrict__ B, int ldb,
                      float* __restrict__ C, int ldc,
                      const float* __restrict__ D, int ldd,
                      float alpha, float beta, int K)
{
    __shared__ __align__(16) float As[2][TBM * ASTR];   // [m][k]
    __shared__ __align__(16) float Bs[2][TBK * BSTR];   // [k][n]

    const int tid = threadIdx.x;
    const int bm = blockIdx.y * TBM;
    const int bn = blockIdx.x * TBN;

    // loader mapping
    const int ar = tid >> 1;            // 0..127
    const int ac = (tid & 1) * 8;       // 0 or 8
    const int br = tid >> 4;            // 0..15
    const int bc = (tid & 15) * 8;      // 0..120

    const float* Ag = A + (size_t)(bm + ar) * lda + ac;
    const float* Bg = B + (size_t)br * ldb + bn + bc;

    const uint32_t sa = (uint32_t)__cvta_generic_to_shared(&As[0][0]);
    const uint32_t sb = (uint32_t)__cvta_generic_to_shared(&Bs[0][0]);
    const uint32_t sa_off = ar * ASTR + ac;
    const uint32_t sb_off = br * BSTR + bc;

    // compute mapping
    const int lane = tid & 31;
    const int w    = tid >> 5;
    const int wm   = (w & 1) * 64;
    const int wn   = (w >> 1) * 32;
    const int gid  = lane >> 2;
    const int tig  = lane & 3;

    float acc[4][4][4];
#pragma unroll
    for (int mm = 0; mm < 4; mm++)
#pragma unroll
        for (int nn = 0; nn < 4; nn++)
#pragma unroll
            for (int r = 0; r < 4; r++) acc[mm][nn][r] = 0.f;

    // prologue: stage 0
    {
        uint32_t da = sa + sa_off * 4;
        cp_async16(da,      Ag);
        cp_async16(da + 16, Ag + 4);
        uint32_t db = sb + sb_off * 4;
        cp_async16(db,      Bg);
        cp_async16(db + 16, Bg + 4);
        cp_commit();
    }

    int buf = 0;
    for (int kt = 0; kt < K; kt += TBK) {
        const bool has_next = (kt + TBK) < K;
        if (has_next) {
            const int nb_ = buf ^ 1;
            const float* Agn = Ag + kt + TBK;
            const float* Bgn = Bg + (size_t)(kt + TBK) * ldb;
            uint32_t da = sa + (nb_ * (TBM * ASTR) + sa_off) * 4;
            cp_async16(da,      Agn);
            cp_async16(da + 16, Agn + 4);
            uint32_t db = sb + (nb_ * (TBK * BSTR) + sb_off) * 4;
            cp_async16(db,      Bgn);
            cp_async16(db + 16, Bgn + 4);
            cp_commit();
            cp_wait<1>();
        } else {
            cp_wait<0>();
        }
        __syncthreads();

        const float* Asb = &As[buf][0];
        const float* Bsb = &Bs[buf][0];
#pragma unroll
        for (int ks = 0; ks < TBK; ks += 8) {
            uint32_t af[4][4], bf[4][2];
#pragma unroll
            for (int mm = 0; mm < 4; mm++) {
                const float* ap = Asb + (wm + mm * 16 + gid) * ASTR + ks + tig;
                af[mm][0] = __float_as_uint(ap[0]);
                af[mm][1] = __float_as_uint(ap[8 * ASTR]);
                af[mm][2] = __float_as_uint(ap[4]);
                af[mm][3] = __float_as_uint(ap[8 * ASTR + 4]);
            }
#pragma unroll
            for (int nn = 0; nn < 4; nn++) {
                const float* bp = Bsb + (ks + tig) * BSTR + wn + nn * 8 + gid;
                bf[nn][0] = __float_as_uint(bp[0]);
                bf[nn][1] = __float_as_uint(bp[4 * BSTR]);
            }
#pragma unroll
            for (int mm = 0; mm < 4; mm++)
#pragma unroll
                for (int nn = 0; nn < 4; nn++) {
                    asm volatile(
                        "mma.sync.aligned.m16n8k8.row.col.f32.tf32.tf32.f32 "
                        "{%0,%1,%2,%3}, {%4,%5,%6,%7}, {%8,%9}, {%0,%1,%2,%3};\n"
                        : "+f"(acc[mm][nn][0]), "+f"(acc[mm][nn][1]),
                          "+f"(acc[mm][nn][2]), "+f"(acc[mm][nn][3])
                        : "r"(af[mm][0]), "r"(af[mm][1]), "r"(af[mm][2]), "r"(af[mm][3]),
                          "r"(bf[nn][0]), "r"(bf[nn][1]));
                }
        }
        __syncthreads();
        buf ^= 1;
    }

    // epilogue
#pragma unroll
    for (int mm = 0; mm < 4; mm++) {
        const int row = bm + wm + mm * 16 + gid;
#pragma unroll
        for (int nn = 0; nn < 4; nn++) {
            const int col = bn + wn + nn * 8 + tig * 2;
            float2 v0, v1;
            v0.x = alpha * acc[mm][nn][0];
            v0.y = alpha * acc[mm][nn][1];
            v1.x = alpha * acc[mm][nn][2];
            v1.y = alpha * acc[mm][nn][3];
            if (beta != 0.f) {
                const float2 d0 = *(const float2*)&D[(size_t)row * ldd + col];
                const float2 d1 = *(const float2*)&D[(size_t)(row + 8) * ldd + col];
                v0.x += beta * d0.x; v0.y += beta * d0.y;
                v1.x += beta * d1.x; v1.y += beta * d1.y;
            }
            *(float2*)&C[(size_t)row * ldc + col]       = v0;
            *(float2*)&C[(size_t)(row + 8) * ldc + col] = v1;
        }
    }
}

// ===================== fp32 GEMM (projections) =====================
#define BMT 128
#define BNT 128
#define BKT 16
#define TM  8
#define TN  8

__global__ __launch_bounds__(256, 2)
void gemm_kernel(int M, int Nc, int K,
                 const float* __restrict__ A, int lda,
                 const float* __restrict__ B, int ldb,
                 float* __restrict__ C, int ldc,
                 const float* __restrict__ D, int ldd,
                 float alpha, float beta,
                 const float* __restrict__ bias)
{
    __shared__ __align__(16) float As[2][BKT][BMT + 4];
    __shared__ __align__(16) float Bs[2][BKT][BNT];

    const int tid = threadIdx.x;
    const int tx = tid & 15;
    const int ty = tid >> 4;
    const int bm = blockIdx.y * BMT;
    const int bn = blockIdx.x * BNT;

    const int arow = tid >> 2;
    const int acol = (tid & 3) << 2;
    const int brow = tid >> 5;
    const int bcol = (tid & 31) << 2;

    float acc[TM][TN];
#pragma unroll
    for (int i = 0; i < TM; i++)
#pragma unroll
        for (int j = 0; j < TN; j++) acc[i][j] = 0.f;

    float4 pa0, pa1, pb0, pb1;

    {
        const float* Ab = A + (size_t)(bm + arow) * lda + acol;
        pa0 = *(const float4*)Ab;
        pa1 = *(const float4*)(Ab + (size_t)64 * lda);
        const int c0 = bn + bcol;
        if (c0 < Nc) {
            const float* Bb = B + (size_t)brow * ldb + c0;
            pb0 = *(const float4*)Bb;
            pb1 = *(const float4*)(Bb + (size_t)8 * ldb);
        } else {
            pb0 = make_float4(0.f, 0.f, 0.f, 0.f);
            pb1 = pb0;
        }
        As[0][acol + 0][arow]      = pa0.x;
        As[0][acol + 1][arow]      = pa0.y;
        As[0][acol + 2][arow]      = pa0.z;
        As[0][acol + 3][arow]      = pa0.w;
        As[0][acol + 0][arow + 64] = pa1.x;
        As[0][acol + 1][arow + 64] = pa1.y;
        As[0][acol + 2][arow + 64] = pa1.z;
        As[0][acol + 3][arow + 64] = pa1.w;
        *(float4*)&Bs[0][brow][bcol]     = pb0;
        *(float4*)&Bs[0][brow + 8][bcol] = pb1;
    }
    __syncthreads();

    int buf = 0;
    for (int kt = 0; kt < K; kt += BKT) {
        const bool has_next = (kt + BKT) < K;
        if (has_next) {
            const int kn = kt + BKT;
            const float* Ab = A + (size_t)(bm + arow) * lda + kn + acol;
            pa0 = *(const float4*)Ab;
            pa1 = *(const float4*)(Ab + (size_t)64 * lda);
            const int c0 = bn + bcol;
            if (c0 < Nc) {
                const float* Bb = B + (size_t)(kn + brow) * ldb + c0;
                pb0 = *(const float4*)Bb;
                pb1 = *(const float4*)(Bb + (size_t)8 * ldb);
            } else {
                pb0 = make_float4(0.f, 0.f, 0.f, 0.f);
                pb1 = pb0;
            }
        }

#pragma unroll
        for (int k = 0; k < BKT; ++k) {
            float rA[TM], rB[TN];
            *(float4*)&rA[0] = *(const float4*)&As[buf][k][ty * TM];
            *(float4*)&rA[4] = *(const float4*)&As[buf][k][ty * TM + 4];
            *(float4*)&rB[0] = *(const float4*)&Bs[buf][k][tx * TN];
            *(float4*)&rB[4] = *(const float4*)&Bs[buf][k][tx * TN + 4];
#pragma unroll
            for (int i = 0; i < TM; i++)
#pragma unroll
                for (int j = 0; j < TN; j++)
                    acc[i][j] = fmaf(rA[i], rB[j], acc[i][j]);
        }

        if (has_next) {
            buf ^= 1;
            As[buf][acol + 0][arow]      = pa0.x;
            As[buf][acol + 1][arow]      = pa0.y;
            As[buf][acol + 2][arow]      = pa0.z;
            As[buf][acol + 3][arow]      = pa0.w;
            As[buf][acol + 0][arow + 64] = pa1.x;
            As[buf][acol + 1][arow + 64] = pa1.y;
            As[buf][acol + 2][arow + 64] = pa1.z;
            As[buf][acol + 3][arow + 64] = pa1.w;
            *(float4*)&Bs[buf][brow][bcol]     = pb0;
            *(float4*)&Bs[buf][brow + 8][bcol] = pb1;
            __syncthreads();
        }
    }

#pragma unroll
    for (int i = 0; i < TM; i++) {
        const int row = bm + ty * TM + i;
#pragma unroll
        for (int j = 0; j < TN; j += 4) {
            const int col = bn + tx * TN + j;
            if (col < Nc) {
                float4 v;
                v.x = alpha * acc[i][j + 0];
                v.y = alpha * acc[i][j + 1];
                v.z = alpha * acc[i][j + 2];
                v.w = alpha * acc[i][j + 3];
                if (beta != 0.f) {
                    const float4 dv = *(const float4*)&D[(size_t)row * ldd + col];
                    v.x += beta * dv.x; v.y += beta * dv.y;
                    v.z += beta * dv.z; v.w += beta * dv.w;
                }
                if (bias) {
                    const float4 bv = *(const float4*)&bias[col];
                    v.x += bv.x; v.y += bv.y; v.z += bv.z; v.w += bv.w;
                }
                *(float4*)&C[(size_t)row * ldc + col] = v;
            }
        }
    }
}

// ============================ elementwise ============================

__device__ __forceinline__ float sigmoidf_(float x) {
    return 1.f / (1.f + expf(-x));
}

__global__ void build_x_kernel(const float* __restrict__ inputs,
                               const float* __restrict__ states,
                               float* __restrict__ X)
{
    int idx = blockIdx.x * blockDim.x + threadIdx.x;
    if (idx >= NN * BD) return;
    const int n = idx / BD;
    const int r = idx - n * BD;
    const int b = r >> 7;
    const int d = r & 127;
    float v;
    if (d < DHH) v = inputs[((size_t)b * NN + n) * DHH + d];
    else         v = states[((size_t)b * NN + n) * DHH + (d - DHH)];
    X[idx] = v;
}

__global__ void gate_kernel(const float* __restrict__ inputs,
                            const float* __restrict__ states,
                            const float* __restrict__ PRE,
                            float* __restrict__ X,
                            float* __restrict__ U)
{
    int idx = blockIdx.x * blockDim.x + threadIdx.x;
    if (idx >= NN * NB * DHH) return;
    const int n = idx / (NB * DHH);
    const int r0 = idx - n * (NB * DHH);
    const int b = r0 >> 6;
    const int d = r0 & 63;
    const size_t prow = (size_t)(n * NB + b) * DCAT;
    const float rr = sigmoidf_(PRE[prow + d]);
    const float uu = sigmoidf_(PRE[prow + DHH + d]);
    U[idx] = uu;
    const float st = states[((size_t)b * NN + n) * DHH + d];
    const size_t xb = (size_t)n * BD + (size_t)b * DCAT;
    X[xb + d]       = inputs[((size_t)b * NN + n) * DHH + d];
    X[xb + DHH + d] = rr * st;
}

__global__ void final_kernel(const float* __restrict__ states,
                             const float* __restrict__ PREC,
                             const float* __restrict__ U,
                             float* __restrict__ out,
                             int out_size)
{
    int idx = blockIdx.x * blockDim.x + threadIdx.x;
    if (idx >= NN * NB * DHH) return;
    const int n = idx / (NB * DHH);
    const int r0 = idx - n * (NB * DHH);
    const int b = r0 >> 6;
    const int d = r0 & 63;
    const float uu = U[idx];
    const float cc = tanhf(PREC[(size_t)(n * NB + b) * DHH + d]);
    const float st = states[((size_t)b * NN + n) * DHH + d];
    const float ns = uu * st + (1.f - uu) * cc;
    const size_t o = ((size_t)b * NN + n) * DHH + d;
    out[o] = ns;
    const size_t total = (size_t)NB * NN * DHH;
    if ((size_t)out_size >= 2 * total) out[total + o] = ns;
}

// ============================ launch ============================

extern "C" void kernel_launch(void* const* d_in, const int* in_sizes, int n_in,
                              void* d_out, int out_size)
{
    const float* inputs   = (const float*)d_in[0];
    const float* states   = (const float*)d_in[1];
    const float* supports = (const float*)d_in[2];
    const float* W_ru     = (const float*)d_in[3];
    const float* b_ru     = (const float*)d_in[4];
    const float* W_c      = (const float*)d_in[5];
    const float* b_c      = (const float*)d_in[6];
    float* out = (float*)d_out;

    float *pX, *pT1, *pT2, *pPRE, *pU;
    cudaGetSymbolAddress((void**)&pX,   g_X);
    cudaGetSymbolAddress((void**)&pT1,  g_T1);
    cudaGetSymbolAddress((void**)&pT2,  g_T2);
    cudaGetSymbolAddress((void**)&pPRE, g_PRE);
    cudaGetSymbolAddress((void**)&pU,   g_U);

    const float* S0 = supports;
    const float* S1 = supports + (size_t)NN * NN;

    const dim3 blk(256);
    const dim3 gBig(BD / TBN, NN / TBM);          // (16, 64)
    const dim3 gProj(1, (NN * NB) / BMT);         // (1, 1024)
    const int MP = NN * NB;                       // 131072

    build_x_kernel<<<(NN * BD + 255) / 256, blk>>>(inputs, states, pX);

    // ---------- ru pre-activation ----------
    gemm_kernel<<<gProj, blk>>>(MP, 2 * DHH, DCAT, pX, DCAT,
                                W_ru + 0 * DCAT * 2 * DHH, 2 * DHH,
                                pPRE, 2 * DHH, (const float*)0, 0, 1.f, 0.f, b_ru);
    tf32_gemm_kernel<<<gBig, blk>>>(S0, NN, pX, BD, pT1, BD,
                                    (const float*)0, 0, 1.f, 0.f, NN);
    gemm_kernel<<<gProj, blk>>>(MP, 2 * DHH, DCAT, pT1, DCAT,
                                W_ru + 1 * DCAT * 2 * DHH, 2 * DHH,
                                pPRE, 2 * DHH, pPRE, 2 * DHH, 1.f, 1.f, (const float*)0);
    tf32_gemm_kernel<<<gBig, blk>>>(S0, NN, pT1, BD, pT2, BD,
                                    pX, BD, 2.f, -1.f, NN);
    gemm_kernel<<<gProj, blk>>>(MP, 2 * DHH, DCAT, pT2, DCAT,
                                W_ru + 2 * DCAT * 2 * DHH, 2 * DHH,
                                pPRE, 2 * DHH, pPRE, 2 * DHH, 1.f, 1.f, (const float*)0);
    tf32_gemm_kernel<<<gBig, blk>>>(S1, NN, pX, BD, pT1, BD,
                                    (const float*)0, 0, 1.f, 0.f, NN);
    gemm_kernel<<<gProj, blk>>>(MP, 2 * DHH, DCAT, pT1, DCAT,
                                W_ru + 3 * DCAT * 2 * DHH, 2 * DHH,
                                pPRE, 2 * DHH, pPRE, 2 * DHH, 1.f, 1.f, (const float*)0);
    tf32_gemm_kernel<<<gBig, blk>>>(S1, NN, pT1, BD, pT2, BD,
                                    pX, BD, 2.f, -1.f, NN);
    gemm_kernel<<<gProj, blk>>>(MP, 2 * DHH, DCAT, pT2, DCAT,
                                W_ru + 4 * DCAT * 2 * DHH, 2 * DHH,
                                pPRE, 2 * DHH, pPRE, 2 * DHH, 1.f, 1.f, (const float*)0);

    // ---------- gates ----------
    gate_kernel<<<(NN * NB * DHH + 255) / 256, blk>>>(inputs, states, pPRE, pX, pU);

    // ---------- c pre-activation ----------
    gemm_kernel<<<gProj, blk>>>(MP, DHH, DCAT, pX, DCAT,
                                W_c + 0 * DCAT * DHH, DHH,
                                pPRE, DHH, (const float*)0, 0, 1.f, 0.f, b_c);
    tf32_gemm_kernel<<<gBig, blk>>>(S0, NN, pX, BD, pT1, BD,
                                    (const float*)0, 0, 1.f, 0.f, NN);
    gemm_kernel<<<gProj, blk>>>(MP, DHH, DCAT, pT1, DCAT,
                                W_c + 1 * DCAT * DHH, DHH,
                                pPRE, DHH, pPRE, DHH, 1.f, 1.f, (const float*)0);
    tf32_gemm_kernel<<<gBig, blk>>>(S0, NN, pT1, BD, pT2, BD,
                                    pX, BD, 2.f, -1.f, NN);
    gemm_kernel<<<gProj, blk>>>(MP, DHH, DCAT, pT2, DCAT,
                                W_c + 2 * DCAT * DHH, DHH,
                                pPRE, DHH, pPRE, DHH, 1.f, 1.f, (const float*)0);
    tf32_gemm_kernel<<<gBig, blk>>>(S1, NN, pX, BD, pT1, BD,
                                    (const float*)0, 0, 1.f, 0.f, NN);
    gemm_kernel<<<gProj, blk>>>(MP, DHH, DCAT, pT1, DCAT,
                                W_c + 3 * DCAT * DHH, DHH,
                                pPRE, DHH, pPRE, DHH, 1.f, 1.f, (const float*)0);
    tf32_gemm_kernel<<<gBig, blk>>>(S1, NN, pT1, BD, pT2, BD,
                                    pX, BD, 2.f, -1.f, NN);
    gemm_kernel<<<gProj, blk>>>(MP, DHH, DCAT, pT2, DCAT,
                                W_c + 4 * DCAT * DHH, DHH,
                                pPRE, DHH, pPRE, DHH, 1.f, 1.f, (const float*)0);

    // ---------- final state ----------
    final_kernel<<<(NN * NB * DHH + 255) / 256, blk>>>(states, pPRE, pU, out, out_size);
}

// round 4
// speedup vs baseline: 6.4181x; 2.0420x over previous
#include <cuda_runtime.h>
#include <cuda_bf16.h>
#include <math.h>
#include <stdint.h>

// Problem constants
#define NB   16
#define NN   8192
#define DHH  64
#define DCAT 128
#define BD   (NB * DCAT)   // 2048

// -------- scratch (device globals) --------
__device__ float g_X [(size_t)NN * BD];
__device__ float g_T1[(size_t)NN * BD];
__device__ float g_T2[(size_t)NN * BD];
__device__ float g_PRE[(size_t)NN * NB * DCAT];
__device__ float g_U [(size_t)NN * NB * DHH];
__device__ __nv_bfloat16 g_Sb [(size_t)2 * NN * NN];   // both supports, bf16
__device__ __nv_bfloat16 g_Xb [(size_t)NN * BD];       // bf16 feature operand
__device__ __nv_bfloat16 g_T1b[(size_t)NN * BD];

// ---------------- async-copy / ldmatrix / mma helpers ----------------
__device__ __forceinline__ void cp_async16(uint32_t dst, const void* src) {
    asm volatile("cp.async.cg.shared.global [%0], [%1], 16;\n"
                 : : "r"(dst), "l"(src) : "memory");
}
__device__ __forceinline__ void cp_async16_pred(uint32_t dst, const void* src, bool pred) {
    const uint32_t sz = pred ? 16u : 0u;
    asm volatile("cp.async.cg.shared.global [%0], [%1], 16, %2;\n"
                 : : "r"(dst), "l"(src), "r"(sz) : "memory");
}
__device__ __forceinline__ void cp_commit() {
    asm volatile("cp.async.commit_group;\n" : : : "memory");
}
template <int N>
__device__ __forceinline__ void cp_wait() {
    asm volatile("cp.async.wait_group %0;\n" : : "n"(N) : "memory");
}
__device__ __forceinline__ void ldsm_x4(uint32_t& r0, uint32_t& r1, uint32_t& r2, uint32_t& r3,
                                        uint32_t addr) {
    asm volatile("ldmatrix.sync.aligned.m8n8.x4.shared.b16 {%0,%1,%2,%3}, [%4];\n"
                 : "=r"(r0), "=r"(r1), "=r"(r2), "=r"(r3) : "r"(addr));
}
__device__ __forceinline__ void ldsm_x4_t(uint32_t& r0, uint32_t& r1, uint32_t& r2, uint32_t& r3,
                                          uint32_t addr) {
    asm volatile("ldmatrix.sync.aligned.m8n8.x4.trans.shared.b16 {%0,%1,%2,%3}, [%4];\n"
                 : "=r"(r0), "=r"(r1), "=r"(r2), "=r"(r3) : "r"(addr));
}
__device__ __forceinline__ void mma_bf16(float* c, const uint32_t* a, uint32_t b0, uint32_t b1) {
    asm volatile("mma.sync.aligned.m16n8k16.row.col.f32.bf16.bf16.f32 "
                 "{%0,%1,%2,%3}, {%4,%5,%6,%7}, {%8,%9}, {%0,%1,%2,%3};\n"
                 : "+f"(c[0]), "+f"(c[1]), "+f"(c[2]), "+f"(c[3])
                 : "r"(a[0]), "r"(a[1]), "r"(a[2]), "r"(a[3]), "r"(b0), "r"(b1));
}

// ===================== bf16 tensor-core GEMM (big S @ X) =====================
// C[M,N] = alpha * A @ B + beta * D   A,B bf16 row-major; C,D fp32.
// M,N multiples of 128; K multiple of 32. Block 128x128x32, 256 thr, 8 warps.
#define HASTR 40    // As row stride (halves): 80B rows -> conflict-free ldmatrix
#define HBSTR 136   // Bs row stride (halves): 272B rows -> conflict-free ldmatrix

__global__ __launch_bounds__(256, 2)
void hgemm_kernel(const __nv_bfloat16* __restrict__ A, int lda,
                  const __nv_bfloat16* __restrict__ B, int ldb,
                  float* __restrict__ C, int ldc,
                  const float* __restrict__ D, int ldd,
                  float alpha, float beta, int K)
{
    __shared__ __align__(16) __nv_bfloat16 As[2][128 * HASTR];
    __shared__ __align__(16) __nv_bfloat16 Bs[2][32 * HBSTR];

    const int tid = threadIdx.x;
    const int bm = blockIdx.y * 128;
    const int bn = blockIdx.x * 128;

    // loaders: A 128x32 halves (2 thr/row x 32B), B 32x128 halves (8 thr/row x 32B)
    const int arow = tid >> 1;
    const int acolh = (tid & 1) * 16;
    const int browk = tid >> 3;
    const int bcolh = (tid & 7) * 16;

    const __nv_bfloat16* Ag = A + (size_t)(bm + arow) * lda + acolh;
    const __nv_bfloat16* Bg = B + (size_t)browk * ldb + bn + bcolh;

    const uint32_t sa = (uint32_t)__cvta_generic_to_shared(&As[0][0]);
    const uint32_t sb = (uint32_t)__cvta_generic_to_shared(&Bs[0][0]);
    const uint32_t sa_off = (arow * HASTR + acolh) * 2;
    const uint32_t sb_off = (browk * HBSTR + bcolh) * 2;

    // compute mapping
    const int lane = tid & 31;
    const int w    = tid >> 5;
    const int wm   = (w & 1) * 64;
    const int wn   = (w >> 1) * 32;
    const int gid  = lane >> 2;
    const int tig  = lane & 3;

    // ldmatrix per-lane bases
    const int a_row_l  = wm + (lane & 15);
    const int a_colh_l = (lane >> 4) << 3;
    const int b_rowk_l = lane & 15;
    const int b_colh_l = wn + ((lane >> 4) << 3);

    float acc[4][4][4];
#pragma unroll
    for (int mm = 0; mm < 4; mm++)
#pragma unroll
        for (int nn = 0; nn < 4; nn++)
#pragma unroll
            for (int r = 0; r < 4; r++) acc[mm][nn][r] = 0.f;

    // prologue: stage 0
    {
        uint32_t da = sa + sa_off;
        cp_async16(da,      Ag);
        cp_async16(da + 16, Ag + 8);
        uint32_t db = sb + sb_off;
        cp_async16(db,      Bg);
        cp_async16(db + 16, Bg + 8);
        cp_commit();
    }

    int buf = 0;
    for (int kt = 0; kt < K; kt += 32) {
        const bool has_next = (kt + 32) < K;
        if (has_next) {
            const int nb_ = buf ^ 1;
            const __nv_bfloat16* Agn = Ag + kt + 32;
            const __nv_bfloat16* Bgn = Bg + (size_t)(kt + 32) * ldb;
            uint32_t da = sa + nb_ * (128 * HASTR * 2) + sa_off;
            cp_async16(da,      Agn);
            cp_async16(da + 16, Agn + 8);
            uint32_t db = sb + nb_ * (32 * HBSTR * 2) + sb_off;
            cp_async16(db,      Bgn);
            cp_async16(db + 16, Bgn + 8);
            cp_commit();
            cp_wait<1>();
        } else {
            cp_wait<0>();
        }
        __syncthreads();

        const uint32_t sa_b = sa + buf * (128 * HASTR * 2);
        const uint32_t sb_b = sb + buf * (32 * HBSTR * 2);

#pragma unroll
        for (int ks = 0; ks < 2; ks++) {
            uint32_t a[4][4];
            uint32_t b[2][4];
#pragma unroll
            for (int mmi = 0; mmi < 4; mmi++) {
                const uint32_t addr = sa_b +
                    ((a_row_l + mmi * 16) * HASTR + ks * 16 + a_colh_l) * 2;
                ldsm_x4(a[mmi][0], a[mmi][1], a[mmi][2], a[mmi][3], addr);
            }
#pragma unroll
            for (int p = 0; p < 2; p++) {
                const uint32_t addr = sb_b +
                    ((ks * 16 + b_rowk_l) * HBSTR + b_colh_l + p * 16) * 2;
                ldsm_x4_t(b[p][0], b[p][1], b[p][2], b[p][3], addr);
            }
#pragma unroll
            for (int mmi = 0; mmi < 4; mmi++)
#pragma unroll
                for (int nni = 0; nni < 4; nni++) {
                    const uint32_t b0 = b[nni >> 1][(nni & 1) * 2];
                    const uint32_t b1 = b[nni >> 1][(nni & 1) * 2 + 1];
                    mma_bf16(acc[mmi][nni], a[mmi], b0, b1);
                }
        }
        __syncthreads();
        buf ^= 1;
    }

    // epilogue
#pragma unroll
    for (int mmi = 0; mmi < 4; mmi++) {
        const int row = bm + wm + mmi * 16 + gid;
#pragma unroll
        for (int nni = 0; nni < 4; nni++) {
            const int col = bn + wn + nni * 8 + tig * 2;
            float2 v0, v1;
            v0.x = alpha * acc[mmi][nni][0];
            v0.y = alpha * acc[mmi][nni][1];
            v1.x = alpha * acc[mmi][nni][2];
            v1.y = alpha * acc[mmi][nni][3];
            if (beta != 0.f) {
                const float2 d0 = *(const float2*)&D[(size_t)row * ldd + col];
                const float2 d1 = *(const float2*)&D[(size_t)(row + 8) * ldd + col];
                v0.x += beta * d0.x; v0.y += beta * d0.y;
                v1.x += beta * d1.x; v1.y += beta * d1.y;
            }
            *(float2*)&C[(size_t)row * ldc + col]       = v0;
            *(float2*)&C[(size_t)(row + 8) * ldc + col] = v1;
        }
    }
}

// ===================== TF32 GEMM (projections, Nc<=128, bias) =====================
#define TBM 128
#define TBN 128
#define TBK 16
#define ASTR 20
#define BSTR 136

__global__ __launch_bounds__(256, 2)
void tf32_gemm_kernel(const float* __restrict__ A, int lda,
                      const float* __restrict__ B, int ldb,
                      float* __restrict__ C, int ldc,
                      const float* __restrict__ D, int ldd,
                      float alpha, float beta, int K, int Nc,
                      const float* __restrict__ bias)
{
    __shared__ __align__(16) float As[2][TBM * ASTR];
    __shared__ __align__(16) float Bs[2][TBK * BSTR];

    const int tid = threadIdx.x;
    const int bm = blockIdx.y * TBM;
    const int bn = blockIdx.x * TBN;

    const int ar = tid >> 1;
    const int ac = (tid & 1) * 8;
    const int br = tid >> 4;
    const int bc = (tid & 15) * 8;

    const bool bp0 = (bn + bc)     < Nc;
    const bool bp1 = (bn + bc + 4) < Nc;

    const float* Ag = A + (size_t)(bm + ar) * lda + ac;
    const float* Bg0 = bp0 ? (B + (size_t)br * ldb + bn + bc)     : B;
    const float* Bg1 = bp1 ? (B + (size_t)br * ldb + bn + bc + 4) : B;

    const uint32_t sa = (uint32_t)__cvta_generic_to_shared(&As[0][0]);
    const uint32_t sb = (uint32_t)__cvta_generic_to_shared(&Bs[0][0]);
    const uint32_t sa_off = ar * ASTR + ac;
    const uint32_t sb_off = br * BSTR + bc;

    const int lane = tid & 31;
    const int w    = tid >> 5;
    const int wm   = (w & 1) * 64;
    const int wn   = (w >> 1) * 32;
    const int gid  = lane >> 2;
    const int tig  = lane & 3;

    float acc[4][4][4];
#pragma unroll
    for (int mm = 0; mm < 4; mm++)
#pragma unroll
        for (int nn = 0; nn < 4; nn++)
#pragma unroll
            for (int r = 0; r < 4; r++) acc[mm][nn][r] = 0.f;

    {
        uint32_t da = sa + sa_off * 4;
        cp_async16(da,      Ag);
        cp_async16(da + 16, Ag + 4);
        uint32_t db = sb + sb_off * 4;
        cp_async16_pred(db,      Bg0, bp0);
        cp_async16_pred(db + 16, Bg1, bp1);
        cp_commit();
    }

    int buf = 0;
    for (int kt = 0; kt < K; kt += TBK) {
        const bool has_next = (kt + TBK) < K;
        if (has_next) {
            const int nb_ = buf ^ 1;
            const float* Agn = Ag + kt + TBK;
            uint32_t da = sa + (nb_ * (TBM * ASTR) + sa_off) * 4;
            cp_async16(da,      Agn);
            cp_async16(da + 16, Agn + 4);
            uint32_t db = sb + (nb_ * (TBK * BSTR) + sb_off) * 4;
            cp_async16_pred(db,      Bg0 + (size_t)(kt + TBK) * (bp0 ? ldb : 0), bp0);
            cp_async16_pred(db + 16, Bg1 + (size_t)(kt + TBK) * (bp1 ? ldb : 0), bp1);
            cp_commit();
            cp_wait<1>();
        } else {
            cp_wait<0>();
        }
        __syncthreads();

        const float* Asb = &As[buf][0];
        const float* Bsb = &Bs[buf][0];
#pragma unroll
        for (int ks = 0; ks < TBK; ks += 8) {
            uint32_t af[4][4], bf[4][2];
#pragma unroll
            for (int mm = 0; mm < 4; mm++) {
                const float* ap = Asb + (wm + mm * 16 + gid) * ASTR + ks + tig;
                af[mm][0] = __float_as_uint(ap[0]);
                af[mm][1] = __float_as_uint(ap[8 * ASTR]);
                af[mm][2] = __float_as_uint(ap[4]);
                af[mm][3] = __float_as_uint(ap[8 * ASTR + 4]);
            }
#pragma unroll
            for (int nn = 0; nn < 4; nn++) {
                const float* bp = Bsb + (ks + tig) * BSTR + wn + nn * 8 + gid;
                bf[nn][0] = __float_as_uint(bp[0]);
                bf[nn][1] = __float_as_uint(bp[4 * BSTR]);
            }
#pragma unroll
            for (int mm = 0; mm < 4; mm++)
#pragma unroll
                for (int nn = 0; nn < 4; nn++) {
                    asm volatile(
                        "mma.sync.aligned.m16n8k8.row.col.f32.tf32.tf32.f32 "
                        "{%0,%1,%2,%3}, {%4,%5,%6,%7}, {%8,%9}, {%0,%1,%2,%3};\n"
                        : "+f"(acc[mm][nn][0]), "+f"(acc[mm][nn][1]),
                          "+f"(acc[mm][nn][2]), "+f"(acc[mm][nn][3])
                        : "r"(af[mm][0]), "r"(af[mm][1]), "r"(af[mm][2]), "r"(af[mm][3]),
                          "r"(bf[nn][0]), "r"(bf[nn][1]));
                }
        }
        __syncthreads();
        buf ^= 1;
    }

#pragma unroll
    for (int mm = 0; mm < 4; mm++) {
        const int row = bm + wm + mm * 16 + gid;
#pragma unroll
        for (int nn = 0; nn < 4; nn++) {
            const int col = bn + wn + nn * 8 + tig * 2;
            if (col < Nc) {
                float2 v0, v1;
                v0.x = alpha * acc[mm][nn][0];
                v0.y = alpha * acc[mm][nn][1];
                v1.x = alpha * acc[mm][nn][2];
                v1.y = alpha * acc[mm][nn][3];
                if (beta != 0.f) {
                    const float2 d0 = *(const float2*)&D[(size_t)row * ldd + col];
                    const float2 d1 = *(const float2*)&D[(size_t)(row + 8) * ldd + col];
                    v0.x += beta * d0.x; v0.y += beta * d0.y;
                    v1.x += beta * d1.x; v1.y += beta * d1.y;
                }
                if (bias) {
                    const float2 bv = *(const float2*)&bias[col];
                    v0.x += bv.x; v0.y += bv.y;
                    v1.x += bv.x; v1.y += bv.y;
                }
                *(float2*)&C[(size_t)row * ldc + col]       = v0;
                *(float2*)&C[(size_t)(row + 8) * ldc + col] = v1;
            }
        }
    }
}

// ============================ conversion / elementwise ============================

__global__ void f2bf_kernel(const float4* __restrict__ src, uint2* __restrict__ dst, size_t n4)
{
    size_t i = (size_t)blockIdx.x * blockDim.x + threadIdx.x;
    if (i >= n4) return;
    const float4 v = src[i];
    const __nv_bfloat162 lo = __floats2bfloat162_rn(v.x, v.y);
    const __nv_bfloat162 hi = __floats2bfloat162_rn(v.z, v.w);
    uint2 o;
    o.x = *reinterpret_cast<const uint32_t*>(&lo);
    o.y = *reinterpret_cast<const uint32_t*>(&hi);
    dst[i] = o;
}

__device__ __forceinline__ float sigmoidf_(float x) {
    return 1.f / (1.f + expf(-x));
}

__global__ void build_x_kernel(const float* __restrict__ inputs,
                               const float* __restrict__ states,
                               float* __restrict__ X)
{
    int idx = blockIdx.x * blockDim.x + threadIdx.x;
    if (idx >= NN * BD) return;
    const int n = idx / BD;
    const int r = idx - n * BD;
    const int b = r >> 7;
    const int d = r & 127;
    float v;
    if (d < DHH) v = inputs[((size_t)b * NN + n) * DHH + d];
    else         v = states[((size_t)b * NN + n) * DHH + (d - DHH)];
    X[idx] = v;
}

__global__ void gate_kernel(const float* __restrict__ inputs,
                            const float* __restrict__ states,
                            const float* __restrict__ PRE,
                            float* __restrict__ X,
                            float* __restrict__ U)
{
    int idx = blockIdx.x * blockDim.x + threadIdx.x;
    if (idx >= NN * NB * DHH) return;
    const int n = idx / (NB * DHH);
    const int r0 = idx - n * (NB * DHH);
    const int b = r0 >> 6;
    const int d = r0 & 63;
    const size_t prow = (size_t)(n * NB + b) * DCAT;
    const float rr = sigmoidf_(PRE[prow + d]);
    const float uu = sigmoidf_(PRE[prow + DHH + d]);
    U[idx] = uu;
    const float st = states[((size_t)b * NN + n) * DHH + d];
    const size_t xb = (size_t)n * BD + (size_t)b * DCAT;
    X[xb + d]       = inputs[((size_t)b * NN + n) * DHH + d];
    X[xb + DHH + d] = rr * st;
}

__global__ void final_kernel(const float* __restrict__ states,
                             const float* __restrict__ PREC,
                             const float* __restrict__ U,
                             float* __restrict__ out,
                             int out_size)
{
    int idx = blockIdx.x * blockDim.x + threadIdx.x;
    if (idx >= NN * NB * DHH) return;
    const int n = idx / (NB * DHH);
    const int r0 = idx - n * (NB * DHH);
    const int b = r0 >> 6;
    const int d = r0 & 63;
    const float uu = U[idx];
    const float cc = tanhf(PREC[(size_t)(n * NB + b) * DHH + d]);
    const float st = states[((size_t)b * NN + n) * DHH + d];
    const float ns = uu * st + (1.f - uu) * cc;
    const size_t o = ((size_t)b * NN + n) * DHH + d;
    out[o] = ns;
    const size_t total = (size_t)NB * NN * DHH;
    if ((size_t)out_size >= 2 * total) out[total + o] = ns;
}

// ============================ launch ============================

extern "C" void kernel_launch(void* const* d_in, const int* in_sizes, int n_in,
                              void* d_out, int out_size)
{
    const float* inputs   = (const float*)d_in[0];
    const float* states   = (const float*)d_in[1];
    const float* supports = (const float*)d_in[2];
    const float* W_ru     = (const float*)d_in[3];
    const float* b_ru     = (const float*)d_in[4];
    const float* W_c      = (const float*)d_in[5];
    const float* b_c      = (const float*)d_in[6];
    float* out = (float*)d_out;

    float *pX, *pT1, *pT2, *pPRE, *pU;
    __nv_bfloat16 *pSb, *pXb, *pT1b;
    cudaGetSymbolAddress((void**)&pX,   g_X);
    cudaGetSymbolAddress((void**)&pT1,  g_T1);
    cudaGetSymbolAddress((void**)&pT2,  g_T2);
    cudaGetSymbolAddress((void**)&pPRE, g_PRE);
    cudaGetSymbolAddress((void**)&pU,   g_U);
    cudaGetSymbolAddress((void**)&pSb,  g_Sb);
    cudaGetSymbolAddress((void**)&pXb,  g_Xb);
    cudaGetSymbolAddress((void**)&pT1b, g_T1b);

    const __nv_bfloat16* S0b = pSb;
    const __nv_bfloat16* S1b = pSb + (size_t)NN * NN;

    const dim3 blk(256);
    const dim3 gBig(BD / 128, NN / 128);          // (16, 64)
    const dim3 gProj(1, (NN * NB) / TBM);         // (1, 1024)
    const int MP = NN * NB;

    const size_t nS4 = (size_t)2 * NN * NN / 4;
    const size_t nX4 = (size_t)NN * BD / 4;
    const int gS = (int)((nS4 + 255) / 256);
    const int gX = (int)((nX4 + 255) / 256);

    // ---- prep: x = [inputs, states]; bf16 casts ----
    build_x_kernel<<<(NN * BD + 255) / 256, blk>>>(inputs, states, pX);
    f2bf_kernel<<<gS, blk>>>((const float4*)supports, (uint2*)pSb, nS4);
    f2bf_kernel<<<gX, blk>>>((const float4*)pX, (uint2*)pXb, nX4);

    // ---------- ru pre-activation ----------
    tf32_gemm_kernel<<<gProj, blk>>>(pX, DCAT, W_ru + 0 * DCAT * 2 * DHH, 2 * DHH,
                                     pPRE, 2 * DHH, (const float*)0, 0,
                                     1.f, 0.f, DCAT, 2 * DHH, b_ru);
    hgemm_kernel<<<gBig, blk>>>(S0b, NN, pXb, BD, pT1, BD,
                                (const float*)0, 0, 1.f, 0.f, NN);
    f2bf_kernel<<<gX, blk>>>((const float4*)pT1, (uint2*)pT1b, nX4);
    tf32_gemm_kernel<<<gProj, blk>>>(pT1, DCAT, W_ru + 1 * DCAT * 2 * DHH, 2 * DHH,
                                     pPRE, 2 * DHH, pPRE, 2 * DHH,
                                     1.f, 1.f, DCAT, 2 * DHH, (const float*)0);
    hgemm_kernel<<<gBig, blk>>>(S0b, NN, pT1b, BD, pT2, BD,
                                pX, BD, 2.f, -1.f, NN);
    tf32_gemm_kernel<<<gProj, blk>>>(pT2, DCAT, W_ru + 2 * DCAT * 2 * DHH, 2 * DHH,
                                     pPRE, 2 * DHH, pPRE, 2 * DHH,
                                     1.f, 1.f, DCAT, 2 * DHH, (const float*)0);
    hgemm_kernel<<<gBig, blk>>>(S1b, NN, pXb, BD, pT1, BD,
                                (const float*)0, 0, 1.f, 0.f, NN);
    f2bf_kernel<<<gX, blk>>>((const float4*)pT1, (uint2*)pT1b, nX4);
    tf32_gemm_kernel<<<gProj, blk>>>(pT1, DCAT, W_ru + 3 * DCAT * 2 * DHH, 2 * DHH,
                                     pPRE, 2 * DHH, pPRE, 2 * DHH,
                                     1.f, 1.f, DCAT, 2 * DHH, (const float*)0);
    hgemm_kernel<<<gBig, blk>>>(S1b, NN, pT1b, BD, pT2, BD,
                                pX, BD, 2.f, -1.f, NN);
    tf32_gemm_kernel<<<gProj, blk>>>(pT2, DCAT, W_ru + 4 * DCAT * 2 * DHH, 2 * DHH,
                                     pPRE, 2 * DHH, pPRE, 2 * DHH,
                                     1.f, 1.f, DCAT, 2 * DHH, (const float*)0);

    // ---------- gates: u, xc = [inputs, r*states] ----------
    gate_kernel<<<(NN * NB * DHH + 255) / 256, blk>>>(inputs, states, pPRE, pX, pU);
    f2bf_kernel<<<gX, blk>>>((const float4*)pX, (uint2*)pXb, nX4);

    // ---------- c pre-activation (Nc = 64) ----------
    tf32_gemm_kernel<<<gProj, blk>>>(pX, DCAT, W_c + 0 * DCAT * DHH, DHH,
                                     pPRE, DHH, (const float*)0, 0,
                                     1.f, 0.f, DCAT, DHH, b_c);
    hgemm_kernel<<<gBig, blk>>>(S0b, NN, pXb, BD, pT1, BD,
                                (const float*)0, 0, 1.f, 0.f, NN);
    f2bf_kernel<<<gX, blk>>>((const float4*)pT1, (uint2*)pT1b, nX4);
    tf32_gemm_kernel<<<gProj, blk>>>(pT1, DCAT, W_c + 1 * DCAT * DHH, DHH,
                                     pPRE, DHH, pPRE, DHH,
                                     1.f, 1.f, DCAT, DHH, (const float*)0);
    hgemm_kernel<<<gBig, blk>>>(S0b, NN, pT1b, BD, pT2, BD,
                                pX, BD, 2.f, -1.f, NN);
    tf32_gemm_kernel<<<gProj, blk>>>(pT2, DCAT, W_c + 2 * DCAT * DHH, DHH,
                                     pPRE, DHH, pPRE, DHH,
                                     1.f, 1.f, DCAT, DHH, (const float*)0);
    hgemm_kernel<<<gBig, blk>>>(S1b, NN, pXb, BD, pT1, BD,
                                (const float*)0, 0, 1.f, 0.f, NN);
    f2bf_kernel<<<gX, blk>>>((const float4*)pT1, (uint2*)pT1b, nX4);
    tf32_gemm_kernel<<<gProj, blk>>>(pT1, DCAT, W_c + 3 * DCAT * DHH, DHH,
                                     pPRE, DHH, pPRE, DHH,
                                     1.f, 1.f, DCAT, DHH, (const float*)0);
    hgemm_kernel<<<gBig, blk>>>(S1b, NN, pT1b, BD, pT2, BD,
                                pX, BD, 2.f, -1.f, NN);
    tf32_gemm_kernel<<<gProj, blk>>>(pT2, DCAT, W_c + 4 * DCAT * DHH, DHH,
                                     pPRE, DHH, pPRE, DHH,
                                     1.f, 1.f, DCAT, DHH, (const float*)0);

    // ---------- final state ----------
    final_kernel<<<(NN * NB * DHH + 255) / 256, blk>>>(states, pPRE, pU, out, out_size);
}

// round 5
// speedup vs baseline: 7.9370x; 1.2367x over previous
#include <cuda_runtime.h>
#include <cuda_bf16.h>
#include <math.h>
#include <stdint.h>

// Problem constants
#define NB   16
#define NN   8192
#define DHH  64
#define DCAT 128
#define BD   (NB * DCAT)   // 2048
#define HALF_W (NB * DHH)  // 1024 : width of one half (inp or st)

// Layout of all feature matrices: (N, 2048) row-major,
//   cols [0,1024)    = inputs-half,  element (n,b,d) at n*2048 + b*64 + d
//   cols [1024,2048) = state-half,   element (n,b,d) at n*2048 + 1024 + b*64 + d

// -------- scratch (device globals) --------
__device__ float g_X  [(size_t)NN * BD];
__device__ float g_T1a[(size_t)NN * BD];   // support-0 hop1
__device__ float g_T2a[(size_t)NN * BD];   // support-0 hop2
__device__ float g_T1c[(size_t)NN * BD];   // support-1 hop1
__device__ float g_T2c[(size_t)NN * BD];   // support-1 hop2
__device__ float g_PRE[(size_t)NN * NB * DCAT];
__device__ float g_U [(size_t)NN * NB * DHH];
__device__ __nv_bfloat16 g_Sb [(size_t)2 * NN * NN];
__device__ __nv_bfloat16 g_Xb [(size_t)NN * BD];
__device__ __nv_bfloat16 g_T1b[(size_t)NN * BD];

// ---------------- async-copy / ldmatrix / mma helpers ----------------
__device__ __forceinline__ void cp_async16(uint32_t dst, const void* src) {
    asm volatile("cp.async.cg.shared.global [%0], [%1], 16;\n"
                 : : "r"(dst), "l"(src) : "memory");
}
__device__ __forceinline__ void cp_async16_pred(uint32_t dst, const void* src, bool pred) {
    const uint32_t sz = pred ? 16u : 0u;
    asm volatile("cp.async.cg.shared.global [%0], [%1], 16, %2;\n"
                 : : "r"(dst), "l"(src), "r"(sz) : "memory");
}
__device__ __forceinline__ void cp_commit() {
    asm volatile("cp.async.commit_group;\n" : : : "memory");
}
template <int N>
__device__ __forceinline__ void cp_wait() {
    asm volatile("cp.async.wait_group %0;\n" : : "n"(N) : "memory");
}
__device__ __forceinline__ void ldsm_x4(uint32_t& r0, uint32_t& r1, uint32_t& r2, uint32_t& r3,
                                        uint32_t addr) {
    asm volatile("ldmatrix.sync.aligned.m8n8.x4.shared.b16 {%0,%1,%2,%3}, [%4];\n"
                 : "=r"(r0), "=r"(r1), "=r"(r2), "=r"(r3) : "r"(addr));
}
__device__ __forceinline__ void ldsm_x4_t(uint32_t& r0, uint32_t& r1, uint32_t& r2, uint32_t& r3,
                                          uint32_t addr) {
    asm volatile("ldmatrix.sync.aligned.m8n8.x4.trans.shared.b16 {%0,%1,%2,%3}, [%4];\n"
                 : "=r"(r0), "=r"(r1), "=r"(r2), "=r"(r3) : "r"(addr));
}
__device__ __forceinline__ void mma_bf16(float* c, const uint32_t* a, uint32_t b0, uint32_t b1) {
    asm volatile("mma.sync.aligned.m16n8k16.row.col.f32.bf16.bf16.f32 "
                 "{%0,%1,%2,%3}, {%4,%5,%6,%7}, {%8,%9}, {%0,%1,%2,%3};\n"
                 : "+f"(c[0]), "+f"(c[1]), "+f"(c[2]), "+f"(c[3])
                 : "r"(a[0]), "r"(a[1]), "r"(a[2]), "r"(a[3]), "r"(b0), "r"(b1));
}

// ===================== bf16 tensor-core GEMM (big S @ X) =====================
// C[M,N] = alpha * A @ B + beta * D   A,B bf16 row-major; C,D fp32.
// M,N multiples of 128; K multiple of 32. Block 128x128x32, 256 thr, 8 warps.
#define HASTR 40
#define HBSTR 136

__global__ __launch_bounds__(256, 2)
void hgemm_kernel(const __nv_bfloat16* __restrict__ A, int lda,
                  const __nv_bfloat16* __restrict__ B, int ldb,
                  float* __restrict__ C, int ldc,
                  const float* __restrict__ D, int ldd,
                  float alpha, float beta, int K)
{
    __shared__ __align__(16) __nv_bfloat16 As[2][128 * HASTR];
    __shared__ __align__(16) __nv_bfloat16 Bs[2][32 * HBSTR];

    const int tid = threadIdx.x;
    const int bm = blockIdx.y * 128;
    const int bn = blockIdx.x * 128;

    const int arow = tid >> 1;
    const int acolh = (tid & 1) * 16;
    const int browk = tid >> 3;
    const int bcolh = (tid & 7) * 16;

    const __nv_bfloat16* Ag = A + (size_t)(bm + arow) * lda + acolh;
    const __nv_bfloat16* Bg = B + (size_t)browk * ldb + bn + bcolh;

    const uint32_t sa = (uint32_t)__cvta_generic_to_shared(&As[0][0]);
    const uint32_t sb = (uint32_t)__cvta_generic_to_shared(&Bs[0][0]);
    const uint32_t sa_off = (arow * HASTR + acolh) * 2;
    const uint32_t sb_off = (browk * HBSTR + bcolh) * 2;

    const int lane = tid & 31;
    const int w    = tid >> 5;
    const int wm   = (w & 1) * 64;
    const int wn   = (w >> 1) * 32;
    const int gid  = lane >> 2;
    const int tig  = lane & 3;

    const int a_row_l  = wm + (lane & 15);
    const int a_colh_l = (lane >> 4) << 3;
    const int b_rowk_l = lane & 15;
    const int b_colh_l = wn + ((lane >> 4) << 3);

    float acc[4][4][4];
#pragma unroll
    for (int mm = 0; mm < 4; mm++)
#pragma unroll
        for (int nn = 0; nn < 4; nn++)
#pragma unroll
            for (int r = 0; r < 4; r++) acc[mm][nn][r] = 0.f;

    {
        uint32_t da = sa + sa_off;
        cp_async16(da,      Ag);
        cp_async16(da + 16, Ag + 8);
        uint32_t db = sb + sb_off;
        cp_async16(db,      Bg);
        cp_async16(db + 16, Bg + 8);
        cp_commit();
    }

    int buf = 0;
    for (int kt = 0; kt < K; kt += 32) {
        const bool has_next = (kt + 32) < K;
        if (has_next) {
            const int nb_ = buf ^ 1;
            const __nv_bfloat16* Agn = Ag + kt + 32;
            const __nv_bfloat16* Bgn = Bg + (size_t)(kt + 32) * ldb;
            uint32_t da = sa + nb_ * (128 * HASTR * 2) + sa_off;
            cp_async16(da,      Agn);
            cp_async16(da + 16, Agn + 8);
            uint32_t db = sb + nb_ * (32 * HBSTR * 2) + sb_off;
            cp_async16(db,      Bgn);
            cp_async16(db + 16, Bgn + 8);
            cp_commit();
            cp_wait<1>();
        } else {
            cp_wait<0>();
        }
        __syncthreads();

        const uint32_t sa_b = sa + buf * (128 * HASTR * 2);
        const uint32_t sb_b = sb + buf * (32 * HBSTR * 2);

#pragma unroll
        for (int ks = 0; ks < 2; ks++) {
            uint32_t a[4][4];
            uint32_t b[2][4];
#pragma unroll
            for (int mmi = 0; mmi < 4; mmi++) {
                const uint32_t addr = sa_b +
                    ((a_row_l + mmi * 16) * HASTR + ks * 16 + a_colh_l) * 2;
                ldsm_x4(a[mmi][0], a[mmi][1], a[mmi][2], a[mmi][3], addr);
            }
#pragma unroll
            for (int p = 0; p < 2; p++) {
                const uint32_t addr = sb_b +
                    ((ks * 16 + b_rowk_l) * HBSTR + b_colh_l + p * 16) * 2;
                ldsm_x4_t(b[p][0], b[p][1], b[p][2], b[p][3], addr);
            }
#pragma unroll
            for (int mmi = 0; mmi < 4; mmi++)
#pragma unroll
                for (int nni = 0; nni < 4; nni++) {
                    const uint32_t b0 = b[nni >> 1][(nni & 1) * 2];
                    const uint32_t b1 = b[nni >> 1][(nni & 1) * 2 + 1];
                    mma_bf16(acc[mmi][nni], a[mmi], b0, b1);
                }
        }
        __syncthreads();
        buf ^= 1;
    }

#pragma unroll
    for (int mmi = 0; mmi < 4; mmi++) {
        const int row = bm + wm + mmi * 16 + gid;
#pragma unroll
        for (int nni = 0; nni < 4; nni++) {
            const int col = bn + wn + nni * 8 + tig * 2;
            float2 v0, v1;
            v0.x = alpha * acc[mmi][nni][0];
            v0.y = alpha * acc[mmi][nni][1];
            v1.x = alpha * acc[mmi][nni][2];
            v1.y = alpha * acc[mmi][nni][3];
            if (beta != 0.f) {
                const float2 d0 = *(const float2*)&D[(size_t)row * ldd + col];
                const float2 d1 = *(const float2*)&D[(size_t)(row + 8) * ldd + col];
                v0.x += beta * d0.x; v0.y += beta * d0.y;
                v1.x += beta * d1.x; v1.y += beta * d1.y;
            }
            *(float2*)&C[(size_t)row * ldc + col]       = v0;
            *(float2*)&C[(size_t)(row + 8) * ldc + col] = v1;
        }
    }
}

// ============ TF32 projection GEMM: feature (halves layout) @ W-block ============
// C[M=131072, Nc] (+)= A_feat @ W + bias.   K = 128 fixed (64 inp + 64 st).
// A is a (N, 2048) halves-layout feature buffer; logical row m = n*16 + b reads
// inp cols from A[rowbase + k] (k<64) and st cols from A[rowbase + 1024 + k-64].
#define TBM 128
#define TBK 16
#define ASTR 20
#define BSTR 136

__global__ __launch_bounds__(256, 2)
void tf32_proj_kernel(const float* __restrict__ A,
                      const float* __restrict__ W, int ldw, int Nc,
                      float* __restrict__ C, int accum,
                      const float* __restrict__ bias)
{
    __shared__ __align__(16) float As[2][TBM * ASTR];
    __shared__ __align__(16) float Bs[2][TBK * BSTR];

    const int tid = threadIdx.x;
    const int bm = blockIdx.y * TBM;

    const int ar = tid >> 1;
    const int ac = (tid & 1) * 8;
    const int br = tid >> 4;
    const int bc = (tid & 15) * 8;

    const int m = bm + ar;
    const size_t rowbase = ((size_t)(m >> 4)) * 2048 + (size_t)(m & 15) * 64;

    const bool bp0 = bc < Nc;
    const bool bp1 = (bc + 4) < Nc;

    const uint32_t sa = (uint32_t)__cvta_generic_to_shared(&As[0][0]);
    const uint32_t sb = (uint32_t)__cvta_generic_to_shared(&Bs[0][0]);
    const uint32_t sa_off = ar * ASTR + ac;
    const uint32_t sb_off = br * BSTR + bc;

    const int lane = tid & 31;
    const int w    = tid >> 5;
    const int wm   = (w & 1) * 64;
    const int wn   = (w >> 1) * 32;
    const int gid  = lane >> 2;
    const int tig  = lane & 3;

    float acc[4][4][4];
#pragma unroll
    for (int mm = 0; mm < 4; mm++)
#pragma unroll
        for (int nn = 0; nn < 4; nn++)
#pragma unroll
            for (int r = 0; r < 4; r++) acc[mm][nn][r] = 0.f;

    // A source address for k-tile kt (this thread covers kk = kt+ac .. +7, same half)
    // kk < 64 -> inp half; else st half at +1024
    {
        const int kk = 0 + ac;
        const float* srcA = A + rowbase + (kk < 64 ? kk : 1024 + kk - 64);
        uint32_t da = sa + sa_off * 4;
        cp_async16(da,      srcA);
        cp_async16(da + 16, srcA + 4);
        uint32_t db = sb + sb_off * 4;
        cp_async16_pred(db,      W + (size_t)br * ldw + bc,     bp0);
        cp_async16_pred(db + 16, W + (size_t)br * ldw + bc + 4, bp1);
        cp_commit();
    }

    int buf = 0;
    for (int kt = 0; kt < 128; kt += TBK) {
        const bool has_next = (kt + TBK) < 128;
        if (has_next) {
            const int nb_ = buf ^ 1;
            const int kt2 = kt + TBK;
            const int kk = kt2 + ac;
            const float* srcA = A + rowbase + (kk < 64 ? kk : 1024 + kk - 64);
            uint32_t da = sa + (nb_ * (TBM * ASTR) + sa_off) * 4;
            cp_async16(da,      srcA);
            cp_async16(da + 16, srcA + 4);
            uint32_t db = sb + (nb_ * (TBK * BSTR) + sb_off) * 4;
            cp_async16_pred(db,      W + (size_t)(kt2 + br) * ldw + bc,     bp0);
            cp_async16_pred(db + 16, W + (size_t)(kt2 + br) * ldw + bc + 4, bp1);
            cp_commit();
            cp_wait<1>();
        } else {
            cp_wait<0>();
        }
        __syncthreads();

        const float* Asb = &As[buf][0];
        const float* Bsb = &Bs[buf][0];
#pragma unroll
        for (int ks = 0; ks < TBK; ks += 8) {
            uint32_t af[4][4], bf[4][2];
#pragma unroll
            for (int mm = 0; mm < 4; mm++) {
                const float* ap = Asb + (wm + mm * 16 + gid) * ASTR + ks + tig;
                af[mm][0] = __float_as_uint(ap[0]);
                af[mm][1] = __float_as_uint(ap[8 * ASTR]);
                af[mm][2] = __float_as_uint(ap[4]);
                af[mm][3] = __float_as_uint(ap[8 * ASTR + 4]);
            }
#pragma unroll
            for (int nn = 0; nn < 4; nn++) {
                const float* bp = Bsb + (ks + tig) * BSTR + wn + nn * 8 + gid;
                bf[nn][0] = __float_as_uint(bp[0]);
                bf[nn][1] = __float_as_uint(bp[4 * BSTR]);
            }
#pragma unroll
            for (int mm = 0; mm < 4; mm++)
#pragma unroll
                for (int nn = 0; nn < 4; nn++) {
                    asm volatile(
                        "mma.sync.aligned.m16n8k8.row.col.f32.tf32.tf32.f32 "
                        "{%0,%1,%2,%3}, {%4,%5,%6,%7}, {%8,%9}, {%0,%1,%2,%3};\n"
                        : "+f"(acc[mm][nn][0]), "+f"(acc[mm][nn][1]),
                          "+f"(acc[mm][nn][2]), "+f"(acc[mm][nn][3])
                        : "r"(af[mm][0]), "r"(af[mm][1]), "r"(af[mm][2]), "r"(af[mm][3]),
                          "r"(bf[nn][0]), "r"(bf[nn][1]));
                }
        }
        __syncthreads();
        buf ^= 1;
    }

#pragma unroll
    for (int mm = 0; mm < 4; mm++) {
        const int row = bm + wm + mm * 16 + gid;
#pragma unroll
        for (int nn = 0; nn < 4; nn++) {
            const int col = wn + nn * 8 + tig * 2;
            if (col < Nc) {
                float2 v0, v1;
                v0.x = acc[mm][nn][0];
                v0.y = acc[mm][nn][1];
                v1.x = acc[mm][nn][2];
                v1.y = acc[mm][nn][3];
                if (accum) {
                    const float2 d0 = *(const float2*)&C[(size_t)row * Nc + col];
                    const float2 d1 = *(const float2*)&C[(size_t)(row + 8) * Nc + col];
                    v0.x += d0.x; v0.y += d0.y;
                    v1.x += d1.x; v1.y += d1.y;
                }
                if (bias) {
                    const float2 bv = *(const float2*)&bias[col];
                    v0.x += bv.x; v0.y += bv.y;
                    v1.x += bv.x; v1.y += bv.y;
                }
                *(float2*)&C[(size_t)row * Nc + col]       = v0;
                *(float2*)&C[(size_t)(row + 8) * Nc + col] = v1;
            }
        }
    }
}

// ============================ conversion / elementwise ============================

__global__ void f2bf_kernel(const float4* __restrict__ src, uint2* __restrict__ dst, size_t n4)
{
    size_t i = (size_t)blockIdx.x * blockDim.x + threadIdx.x;
    if (i >= n4) return;
    const float4 v = src[i];
    const __nv_bfloat162 lo = __floats2bfloat162_rn(v.x, v.y);
    const __nv_bfloat162 hi = __floats2bfloat162_rn(v.z, v.w);
    uint2 o;
    o.x = *reinterpret_cast<const uint32_t*>(&lo);
    o.y = *reinterpret_cast<const uint32_t*>(&hi);
    dst[i] = o;
}

// Cast only the state-half (cols 1024..2047) of a (N,2048) buffer.
__global__ void f2bf_st_kernel(const float4* __restrict__ src, uint2* __restrict__ dst)
{
    size_t i = (size_t)blockIdx.x * blockDim.x + threadIdx.x;      // over N*1024/4
    const size_t total = (size_t)NN * HALF_W / 4;
    if (i >= total) return;
    const size_t n = i >> 8;            // 256 float4 per half-row
    const size_t c = i & 255;
    const size_t off = n * 512 + 256 + c;   // full row = 512 float4; st half at +256
    const float4 v = src[off];
    const __nv_bfloat162 lo = __floats2bfloat162_rn(v.x, v.y);
    const __nv_bfloat162 hi = __floats2bfloat162_rn(v.z, v.w);
    uint2 o;
    o.x = *reinterpret_cast<const uint32_t*>(&lo);
    o.y = *reinterpret_cast<const uint32_t*>(&hi);
    dst[off] = o;
}

__device__ __forceinline__ float sigmoidf_(float x) {
    return 1.f / (1.f + expf(-x));
}

// X halves layout: inp at n*2048 + b*64 + d ; st at +1024
__global__ void build_x_kernel(const float* __restrict__ inputs,
                               const float* __restrict__ states,
                               float* __restrict__ X)
{
    int idx = blockIdx.x * blockDim.x + threadIdx.x;
    if (idx >= NN * BD) return;
    const int n = idx >> 11;
    const int r = idx & 2047;
    float v;
    if (r < HALF_W) {
        const int b = r >> 6, d = r & 63;
        v = inputs[((size_t)b * NN + n) * DHH + d];
    } else {
        const int r2 = r - HALF_W;
        const int b = r2 >> 6, d = r2 & 63;
        v = states[((size_t)b * NN + n) * DHH + d];
    }
    X[idx] = v;
}

// From PRE (ru preact, (N*B,128)): r=sigmoid(:64), u=sigmoid(64:)
// store u; overwrite X st-half with r*states (inp half untouched)
__global__ void gate_kernel(const float* __restrict__ states,
                            const float* __restrict__ PRE,
                            float* __restrict__ X,
                            float* __restrict__ U)
{
    int idx = blockIdx.x * blockDim.x + threadIdx.x;
    if (idx >= NN * NB * DHH) return;
    const int n = idx / (NB * DHH);
    const int r0 = idx - n * (NB * DHH);
    const int b = r0 >> 6;
    const int d = r0 & 63;
    const size_t prow = (size_t)(n * NB + b) * DCAT;
    const float rr = sigmoidf_(PRE[prow + d]);
    const float uu = sigmoidf_(PRE[prow + DHH + d]);
    U[idx] = uu;
    const float st = states[((size_t)b * NN + n) * DHH + d];
    X[(size_t)n * BD + HALF_W + (size_t)b * DHH + d] = rr * st;
}

__global__ void final_kernel(const float* __restrict__ states,
                             const float* __restrict__ PREC,
                             const float* __restrict__ U,
                             float* __restrict__ out,
                             int out_size)
{
    int idx = blockIdx.x * blockDim.x + threadIdx.x;
    if (idx >= NN * NB * DHH) return;
    const int n = idx / (NB * DHH);
    const int r0 = idx - n * (NB * DHH);
    const int b = r0 >> 6;
    const int d = r0 & 63;
    const float uu = U[idx];
    const float cc = tanhf(PREC[(size_t)(n * NB + b) * DHH + d]);
    const float st = states[((size_t)b * NN + n) * DHH + d];
    const float ns = uu * st + (1.f - uu) * cc;
    const size_t o = ((size_t)b * NN + n) * DHH + d;
    out[o] = ns;
    const size_t total = (size_t)NB * NN * DHH;
    if ((size_t)out_size >= 2 * total) out[total + o] = ns;
}

// ============================ launch ============================

extern "C" void kernel_launch(void* const* d_in, const int* in_sizes, int n_in,
                              void* d_out, int out_size)
{
    const float* inputs   = (const float*)d_in[0];
    const float* states   = (const float*)d_in[1];
    const float* supports = (const float*)d_in[2];
    const float* W_ru     = (const float*)d_in[3];
    const float* b_ru     = (const float*)d_in[4];
    const float* W_c      = (const float*)d_in[5];
    const float* b_c      = (const float*)d_in[6];
    float* out = (float*)d_out;

    float *pX, *pT1a, *pT2a, *pT1c, *pT2c, *pPRE, *pU;
    __nv_bfloat16 *pSb, *pXb, *pT1b;
    cudaGetSymbolAddress((void**)&pX,   g_X);
    cudaGetSymbolAddress((void**)&pT1a, g_T1a);
    cudaGetSymbolAddress((void**)&pT2a, g_T2a);
    cudaGetSymbolAddress((void**)&pT1c, g_T1c);
    cudaGetSymbolAddress((void**)&pT2c, g_T2c);
    cudaGetSymbolAddress((void**)&pPRE, g_PRE);
    cudaGetSymbolAddress((void**)&pU,   g_U);
    cudaGetSymbolAddress((void**)&pSb,  g_Sb);
    cudaGetSymbolAddress((void**)&pXb,  g_Xb);
    cudaGetSymbolAddress((void**)&pT1b, g_T1b);

    const __nv_bfloat16* S0b = pSb;
    const __nv_bfloat16* S1b = pSb + (size_t)NN * NN;

    const dim3 blk(256);
    const dim3 gFull(BD / 128, NN / 128);           // (16, 64): width-2048 hgemm
    const dim3 gHalf(HALF_W / 128, NN / 128);       // (8, 64) : width-1024 hgemm
    const dim3 gProj(1, (NN * NB) / TBM);           // (1, 1024)

    const size_t nS4 = (size_t)2 * NN * NN / 4;
    const size_t nX4 = (size_t)NN * BD / 4;
    const size_t nH4 = (size_t)NN * HALF_W / 4;
    const int gS = (int)((nS4 + 255) / 256);
    const int gX = (int)((nX4 + 255) / 256);
    const int gH = (int)((nH4 + 255) / 256);

    // W block pointers
    const float* Wru0 = W_ru;
    const float* Wru1 = W_ru + 1 * DCAT * 2 * DHH;
    const float* Wru2 = W_ru + 2 * DCAT * 2 * DHH;
    const float* Wru3 = W_ru + 3 * DCAT * 2 * DHH;
    const float* Wru4 = W_ru + 4 * DCAT * 2 * DHH;
    const float* Wc0 = W_c;
    const float* Wc1 = W_c + 1 * DCAT * DHH;
    const float* Wc2 = W_c + 2 * DCAT * DHH;
    const float* Wc3 = W_c + 3 * DCAT * DHH;
    const float* Wc4 = W_c + 4 * DCAT * DHH;

    // ---- prep ----
    build_x_kernel<<<(NN * BD + 255) / 256, blk>>>(inputs, states, pX);
    f2bf_kernel<<<gS, blk>>>((const float4*)supports, (uint2*)pSb, nS4);
    f2bf_kernel<<<gX, blk>>>((const float4*)pX, (uint2*)pXb, nX4);

    // ---------- phase 1: ru pre-activation (full width 2048) ----------
    tf32_proj_kernel<<<gProj, blk>>>(pX, Wru0, 2 * DHH, 2 * DHH, pPRE, 0, b_ru);

    hgemm_kernel<<<gFull, blk>>>(S0b, NN, pXb, BD, pT1a, BD,
                                 (const float*)0, 0, 1.f, 0.f, NN);
    f2bf_kernel<<<gX, blk>>>((const float4*)pT1a, (uint2*)pT1b, nX4);
    tf32_proj_kernel<<<gProj, blk>>>(pT1a, Wru1, 2 * DHH, 2 * DHH, pPRE, 1, (const float*)0);

    hgemm_kernel<<<gFull, blk>>>(S0b, NN, pT1b, BD, pT2a, BD,
                                 pX, BD, 2.f, -1.f, NN);
    tf32_proj_kernel<<<gProj, blk>>>(pT2a, Wru2, 2 * DHH, 2 * DHH, pPRE, 1, (const float*)0);

    hgemm_kernel<<<gFull, blk>>>(S1b, NN, pXb, BD, pT1c, BD,
                                 (const float*)0, 0, 1.f, 0.f, NN);
    f2bf_kernel<<<gX, blk>>>((const float4*)pT1c, (uint2*)pT1b, nX4);
    tf32_proj_kernel<<<gProj, blk>>>(pT1c, Wru3, 2 * DHH, 2 * DHH, pPRE, 1, (const float*)0);

    hgemm_kernel<<<gFull, blk>>>(S1b, NN, pT1b, BD, pT2c, BD,
                                 pX, BD, 2.f, -1.f, NN);
    tf32_proj_kernel<<<gProj, blk>>>(pT2c, Wru4, 2 * DHH, 2 * DHH, pPRE, 1, (const float*)0);

    // ---------- gates: u ; X st-half := r*states ----------
    gate_kernel<<<(NN * NB * DHH + 255) / 256, blk>>>(states, pPRE, pX, pU);
    f2bf_st_kernel<<<gH, blk>>>((const float4*)pX, (uint2*)pXb);

    // ---------- phase 2: c pre-activation (st halves only, width 1024) ----------
    // inp halves of X / T1a / T2a / T1c / T2c are reused from phase 1.
    tf32_proj_kernel<<<gProj, blk>>>(pX, Wc0, DHH, DHH, pPRE, 0, b_c);

    hgemm_kernel<<<gHalf, blk>>>(S0b, NN, pXb + HALF_W, BD, pT1a + HALF_W, BD,
                                 (const float*)0, 0, 1.f, 0.f, NN);
    f2bf_st_kernel<<<gH, blk>>>((const float4*)pT1a, (uint2*)pT1b);
    tf32_proj_kernel<<<gProj, blk>>>(pT1a, Wc1, DHH, DHH, pPRE, 1, (const float*)0);

    hgemm_kernel<<<gHalf, blk>>>(S0b, NN, pT1b + HALF_W, BD, pT2a + HALF_W, BD,
                                 pX + HALF_W, BD, 2.f, -1.f, NN);
    tf32_proj_kernel<<<gProj, blk>>>(pT2a, Wc2, DHH, DHH, pPRE, 1, (const float*)0);

    hgemm_kernel<<<gHalf, blk>>>(S1b, NN, pXb + HALF_W, BD, pT1c + HALF_W, BD,
                                 (const float*)0, 0, 1.f, 0.f, NN);
    f2bf_st_kernel<<<gH, blk>>>((const float4*)pT1c, (uint2*)pT1b);
    tf32_proj_kernel<<<gProj, blk>>>(pT1c, Wc3, DHH, DHH, pPRE, 1, (const float*)0);

    hgemm_kernel<<<gHalf, blk>>>(S1b, NN, pT1b + HALF_W, BD, pT2c + HALF_W, BD,
                                 pX + HALF_W, BD, 2.f, -1.f, NN);
    tf32_proj_kernel<<<gProj, blk>>>(pT2c, Wc4, DHH, DHH, pPRE, 1, (const float*)0);

    // ---------- final state ----------
    final_kernel<<<(NN * NB * DHH + 255) / 256, blk>>>(states, pPRE, pU, out, out_size);
}

// round 6
// speedup vs baseline: 9.9992x; 1.2598x over previous
#include <cuda_runtime.h>
#include <cuda_bf16.h>
#include <math.h>
#include <stdint.h>

// Problem constants
#define NB   16
#define NN   8192
#define DHH  64
#define DCAT 128
#define BD   (NB * DCAT)   // 2048
#define HALF_W (NB * DHH)  // 1024

// Feature layout: (N, 2048) row-major; inp half at n*2048 + b*64 + d, st half at +1024.

// -------- scratch (device globals) --------
__device__ float g_X  [(size_t)NN * BD];
__device__ float g_T1a[(size_t)NN * BD];
__device__ float g_T2a[(size_t)NN * BD];
__device__ float g_T1c[(size_t)NN * BD];
__device__ float g_T2c[(size_t)NN * BD];
__device__ float g_PRE[(size_t)NN * NB * DCAT];
__device__ float g_U [(size_t)NN * NB * DHH];
__device__ __nv_bfloat16 g_Sb [(size_t)2 * NN * NN];
__device__ __nv_bfloat16 g_Xb [(size_t)NN * BD];
__device__ __nv_bfloat16 g_T1b[(size_t)NN * BD];

// ---------------- helpers ----------------
__device__ __forceinline__ void cp_async16(uint32_t dst, const void* src) {
    asm volatile("cp.async.cg.shared.global [%0], [%1], 16;\n"
                 : : "r"(dst), "l"(src) : "memory");
}
__device__ __forceinline__ void cp_async16_pred(uint32_t dst, const void* src, bool pred) {
    const uint32_t sz = pred ? 16u : 0u;
    asm volatile("cp.async.cg.shared.global [%0], [%1], 16, %2;\n"
                 : : "r"(dst), "l"(src), "r"(sz) : "memory");
}
__device__ __forceinline__ void cp_commit() {
    asm volatile("cp.async.commit_group;\n" : : : "memory");
}
template <int N>
__device__ __forceinline__ void cp_wait() {
    asm volatile("cp.async.wait_group %0;\n" : : "n"(N) : "memory");
}
__device__ __forceinline__ void ldsm_x4(uint32_t& r0, uint32_t& r1, uint32_t& r2, uint32_t& r3,
                                        uint32_t addr) {
    asm volatile("ldmatrix.sync.aligned.m8n8.x4.shared.b16 {%0,%1,%2,%3}, [%4];\n"
                 : "=r"(r0), "=r"(r1), "=r"(r2), "=r"(r3) : "r"(addr));
}
__device__ __forceinline__ void ldsm_x4_t(uint32_t& r0, uint32_t& r1, uint32_t& r2, uint32_t& r3,
                                          uint32_t addr) {
    asm volatile("ldmatrix.sync.aligned.m8n8.x4.trans.shared.b16 {%0,%1,%2,%3}, [%4];\n"
                 : "=r"(r0), "=r"(r1), "=r"(r2), "=r"(r3) : "r"(addr));
}
__device__ __forceinline__ void mma_bf16(float* c, const uint32_t* a, uint32_t b0, uint32_t b1) {
    asm volatile("mma.sync.aligned.m16n8k16.row.col.f32.bf16.bf16.f32 "
                 "{%0,%1,%2,%3}, {%4,%5,%6,%7}, {%8,%9}, {%0,%1,%2,%3};\n"
                 : "+f"(c[0]), "+f"(c[1]), "+f"(c[2]), "+f"(c[3])
                 : "r"(a[0]), "r"(a[1]), "r"(a[2]), "r"(a[3]), "r"(b0), "r"(b1));
}

// ===================== bf16 GEMM, 4-stage pipeline =====================
// C[M,N] = alpha*A@B + beta*D ; optional bf16 mirror Cb (same layout/ld as C).
#define HASTR 40
#define HBSTR 136
#define NSTG  4
#define ASZH  (128 * HASTR)          // halves per A stage
#define BSZH  (32 * HBSTR)           // halves per B stage
#define HG_SMEM ((ASZH + BSZH) * 2 * NSTG)   // bytes = 75776

__global__ __launch_bounds__(256, 2)
void hgemm_kernel(const __nv_bfloat16* __restrict__ A, int lda,
                  const __nv_bfloat16* __restrict__ B, int ldb,
                  float* __restrict__ C, int ldc,
                  const float* __restrict__ D, int ldd,
                  __nv_bfloat16* __restrict__ Cb,
                  float alpha, float beta, int K)
{
    extern __shared__ __align__(16) char smem_raw[];
    __nv_bfloat16* Asm = (__nv_bfloat16*)smem_raw;            // NSTG * ASZH
    __nv_bfloat16* Bsm = Asm + NSTG * ASZH;                   // NSTG * BSZH

    const int tid = threadIdx.x;
    const int bm = blockIdx.y * 128;
    const int bn = blockIdx.x * 128;

    const int arow = tid >> 1;
    const int acolh = (tid & 1) * 16;
    const int browk = tid >> 3;
    const int bcolh = (tid & 7) * 16;

    const __nv_bfloat16* Ag = A + (size_t)(bm + arow) * lda + acolh;
    const __nv_bfloat16* Bg = B + (size_t)browk * ldb + bn + bcolh;

    const uint32_t sa = (uint32_t)__cvta_generic_to_shared(Asm);
    const uint32_t sb = (uint32_t)__cvta_generic_to_shared(Bsm);
    const uint32_t sa_off = (arow * HASTR + acolh) * 2;
    const uint32_t sb_off = (browk * HBSTR + bcolh) * 2;

    const int lane = tid & 31;
    const int w    = tid >> 5;
    const int wm   = (w & 1) * 64;
    const int wn   = (w >> 1) * 32;
    const int gid  = lane >> 2;
    const int tig  = lane & 3;

    const int a_row_l  = wm + (lane & 15);
    const int a_colh_l = (lane >> 4) << 3;
    const int b_rowk_l = lane & 15;
    const int b_colh_l = wn + ((lane >> 4) << 3);

    float acc[4][4][4];
#pragma unroll
    for (int mm = 0; mm < 4; mm++)
#pragma unroll
        for (int nn = 0; nn < 4; nn++)
#pragma unroll
            for (int r = 0; r < 4; r++) acc[mm][nn][r] = 0.f;

    const int ntiles = K >> 5;

    // prologue: stage 0..NSTG-2
#pragma unroll
    for (int s = 0; s < NSTG - 1; ++s) {
        if (s < ntiles) {
            const int kt = s * 32;
            uint32_t da = sa + s * (ASZH * 2) + sa_off;
            cp_async16(da,      Ag + kt);
            cp_async16(da + 16, Ag + kt + 8);
            uint32_t db = sb + s * (BSZH * 2) + sb_off;
            cp_async16(db,      Bg + (size_t)kt * ldb);
            cp_async16(db + 16, Bg + (size_t)kt * ldb + 8);
        }
        cp_commit();
    }

    for (int i = 0; i < ntiles; ++i) {
        cp_wait<NSTG - 2>();
        __syncthreads();

        const int buf = i & (NSTG - 1);
        const uint32_t sa_b = sa + buf * (ASZH * 2);
        const uint32_t sb_b = sb + buf * (BSZH * 2);

#pragma unroll
        for (int ks = 0; ks < 2; ks++) {
            uint32_t a[4][4];
            uint32_t b[2][4];
#pragma unroll
            for (int mmi = 0; mmi < 4; mmi++) {
                const uint32_t addr = sa_b +
                    ((a_row_l + mmi * 16) * HASTR + ks * 16 + a_colh_l) * 2;
                ldsm_x4(a[mmi][0], a[mmi][1], a[mmi][2], a[mmi][3], addr);
            }
#pragma unroll
            for (int p = 0; p < 2; p++) {
                const uint32_t addr = sb_b +
                    ((ks * 16 + b_rowk_l) * HBSTR + b_colh_l + p * 16) * 2;
                ldsm_x4_t(b[p][0], b[p][1], b[p][2], b[p][3], addr);
            }
#pragma unroll
            for (int mmi = 0; mmi < 4; mmi++)
#pragma unroll
                for (int nni = 0; nni < 4; nni++) {
                    const uint32_t b0 = b[nni >> 1][(nni & 1) * 2];
                    const uint32_t b1 = b[nni >> 1][(nni & 1) * 2 + 1];
                    mma_bf16(acc[mmi][nni], a[mmi], b0, b1);
                }
        }

        const int nt = i + NSTG - 1;
        if (nt < ntiles) {
            const int nb_ = nt & (NSTG - 1);
            const int kt = nt * 32;
            uint32_t da = sa + nb_ * (ASZH * 2) + sa_off;
            cp_async16(da,      Ag + kt);
            cp_async16(da + 16, Ag + kt + 8);
            uint32_t db = sb + nb_ * (BSZH * 2) + sb_off;
            cp_async16(db,      Bg + (size_t)kt * ldb);
            cp_async16(db + 16, Bg + (size_t)kt * ldb + 8);
        }
        cp_commit();
    }

    // epilogue
#pragma unroll
    for (int mmi = 0; mmi < 4; mmi++) {
        const int row = bm + wm + mmi * 16 + gid;
#pragma unroll
        for (int nni = 0; nni < 4; nni++) {
            const int col = bn + wn + nni * 8 + tig * 2;
            float2 v0, v1;
            v0.x = alpha * acc[mmi][nni][0];
            v0.y = alpha * acc[mmi][nni][1];
            v1.x = alpha * acc[mmi][nni][2];
            v1.y = alpha * acc[mmi][nni][3];
            if (beta != 0.f) {
                const float2 d0 = *(const float2*)&D[(size_t)row * ldd + col];
                const float2 d1 = *(const float2*)&D[(size_t)(row + 8) * ldd + col];
                v0.x += beta * d0.x; v0.y += beta * d0.y;
                v1.x += beta * d1.x; v1.y += beta * d1.y;
            }
            *(float2*)&C[(size_t)row * ldc + col]       = v0;
            *(float2*)&C[(size_t)(row + 8) * ldc + col] = v1;
            if (Cb) {
                const __nv_bfloat162 h0 = __floats2bfloat162_rn(v0.x, v0.y);
                const __nv_bfloat162 h1 = __floats2bfloat162_rn(v1.x, v1.y);
                *(__nv_bfloat162*)&Cb[(size_t)row * ldc + col]       = h0;
                *(__nv_bfloat162*)&Cb[(size_t)(row + 8) * ldc + col] = h1;
            }
        }
    }
}

// ============ fused TF32 projection: [X,T1,T2,T1',T2'] (K=640) @ W + bias ============
// C[M=131072, Nc] = sum over 5 feature buffers (halves layout) @ W-blocks + bias.
#define TBM 128
#define TBK 16
#define ASTR 20
#define BSTR 136

__global__ __launch_bounds__(256, 2)
void tf32_proj5_kernel(const float* __restrict__ A0, const float* __restrict__ A1,
                       const float* __restrict__ A2, const float* __restrict__ A3,
                       const float* __restrict__ A4,
                       const float* __restrict__ W, int Nc,
                       float* __restrict__ C,
                       const float* __restrict__ bias)
{
    __shared__ __align__(16) float As[2][TBM * ASTR];
    __shared__ __align__(16) float Bs[2][TBK * BSTR];

    const int tid = threadIdx.x;
    const int bm = blockIdx.y * TBM;

    const int ar = tid >> 1;
    const int ac = (tid & 1) * 8;
    const int br = tid >> 4;
    const int bc = (tid & 15) * 8;

    const int m = bm + ar;
    const size_t rowbase = ((size_t)(m >> 4)) * 2048 + (size_t)(m & 15) * 64;

    const bool bp0 = bc < Nc;
    const bool bp1 = (bc + 4) < Nc;

    const uint32_t sa = (uint32_t)__cvta_generic_to_shared(&As[0][0]);
    const uint32_t sb = (uint32_t)__cvta_generic_to_shared(&Bs[0][0]);
    const uint32_t sa_off = ar * ASTR + ac;
    const uint32_t sb_off = br * BSTR + bc;

    const int lane = tid & 31;
    const int w    = tid >> 5;
    const int wm   = (w & 1) * 64;
    const int wn   = (w >> 1) * 32;
    const int gid  = lane >> 2;
    const int tig  = lane & 3;

    float acc[4][4][4];
#pragma unroll
    for (int mm = 0; mm < 4; mm++)
#pragma unroll
        for (int nn = 0; nn < 4; nn++)
#pragma unroll
            for (int r = 0; r < 4; r++) acc[mm][nn][r] = 0.f;

    // A loader address for global k index kk (this thread's 8-float slice stays in one half)
    auto a_src = [&](int kk) -> const float* {
        const int bufi = kk >> 7;
        const int k = kk & 127;
        const float* Ab = A0;
        if (bufi == 1) Ab = A1;
        else if (bufi == 2) Ab = A2;
        else if (bufi == 3) Ab = A3;
        else if (bufi == 4) Ab = A4;
        return Ab + rowbase + (k < 64 ? k : 1024 + k - 64);
    };

    {
        const float* srcA = a_src(ac);
        uint32_t da = sa + sa_off * 4;
        cp_async16(da,      srcA);
        cp_async16(da + 16, srcA + 4);
        uint32_t db = sb + sb_off * 4;
        cp_async16_pred(db,      W + (size_t)br * Nc + bc,     bp0);
        cp_async16_pred(db + 16, W + (size_t)br * Nc + bc + 4, bp1);
        cp_commit();
    }

    int buf = 0;
    for (int kt = 0; kt < 640; kt += TBK) {
        const bool has_next = (kt + TBK) < 640;
        if (has_next) {
            const int nb_ = buf ^ 1;
            const int kt2 = kt + TBK;
            const float* srcA = a_src(kt2 + ac);
            uint32_t da = sa + (nb_ * (TBM * ASTR) + sa_off) * 4;
            cp_async16(da,      srcA);
            cp_async16(da + 16, srcA + 4);
            uint32_t db = sb + (nb_ * (TBK * BSTR) + sb_off) * 4;
            cp_async16_pred(db,      W + (size_t)(kt2 + br) * Nc + bc,     bp0);
            cp_async16_pred(db + 16, W + (size_t)(kt2 + br) * Nc + bc + 4, bp1);
            cp_commit();
            cp_wait<1>();
        } else {
            cp_wait<0>();
        }
        __syncthreads();

        const float* Asb = &As[buf][0];
        const float* Bsb = &Bs[buf][0];
#pragma unroll
        for (int ks = 0; ks < TBK; ks += 8) {
            uint32_t af[4][4], bf[4][2];
#pragma unroll
            for (int mm = 0; mm < 4; mm++) {
                const float* ap = Asb + (wm + mm * 16 + gid) * ASTR + ks + tig;
                af[mm][0] = __float_as_uint(ap[0]);
                af[mm][1] = __float_as_uint(ap[8 * ASTR]);
                af[mm][2] = __float_as_uint(ap[4]);
                af[mm][3] = __float_as_uint(ap[8 * ASTR + 4]);
            }
#pragma unroll
            for (int nn = 0; nn < 4; nn++) {
                const float* bp = Bsb + (ks + tig) * BSTR + wn + nn * 8 + gid;
                bf[nn][0] = __float_as_uint(bp[0]);
                bf[nn][1] = __float_as_uint(bp[4 * BSTR]);
            }
#pragma unroll
            for (int mm = 0; mm < 4; mm++)
#pragma unroll
                for (int nn = 0; nn < 4; nn++) {
                    asm volatile(
                        "mma.sync.aligned.m16n8k8.row.col.f32.tf32.tf32.f32 "
                        "{%0,%1,%2,%3}, {%4,%5,%6,%7}, {%8,%9}, {%0,%1,%2,%3};\n"
                        : "+f"(acc[mm][nn][0]), "+f"(acc[mm][nn][1]),
                          "+f"(acc[mm][nn][2]), "+f"(acc[mm][nn][3])
                        : "r"(af[mm][0]), "r"(af[mm][1]), "r"(af[mm][2]), "r"(af[mm][3]),
                          "r"(bf[nn][0]), "r"(bf[nn][1]));
                }
        }
        __syncthreads();
        buf ^= 1;
    }

#pragma unroll
    for (int mm = 0; mm < 4; mm++) {
        const int row = bm + wm + mm * 16 + gid;
#pragma unroll
        for (int nn = 0; nn < 4; nn++) {
            const int col = wn + nn * 8 + tig * 2;
            if (col < Nc) {
                float2 v0, v1;
                v0.x = acc[mm][nn][0];
                v0.y = acc[mm][nn][1];
                v1.x = acc[mm][nn][2];
                v1.y = acc[mm][nn][3];
                if (bias) {
                    const float2 bv = *(const float2*)&bias[col];
                    v0.x += bv.x; v0.y += bv.y;
                    v1.x += bv.x; v1.y += bv.y;
                }
                *(float2*)&C[(size_t)row * Nc + col]       = v0;
                *(float2*)&C[(size_t)(row + 8) * Nc + col] = v1;
            }
        }
    }
}

// ============================ conversion / elementwise ============================

__global__ void f2bf_kernel(const float4* __restrict__ src, uint2* __restrict__ dst, size_t n4)
{
    size_t i = (size_t)blockIdx.x * blockDim.x + threadIdx.x;
    if (i >= n4) return;
    const float4 v = src[i];
    const __nv_bfloat162 lo = __floats2bfloat162_rn(v.x, v.y);
    const __nv_bfloat162 hi = __floats2bfloat162_rn(v.z, v.w);
    uint2 o;
    o.x = *reinterpret_cast<const uint32_t*>(&lo);
    o.y = *reinterpret_cast<const uint32_t*>(&hi);
    dst[i] = o;
}

__global__ void f2bf_st_kernel(const float4* __restrict__ src, uint2* __restrict__ dst)
{
    size_t i = (size_t)blockIdx.x * blockDim.x + threadIdx.x;
    const size_t total = (size_t)NN * HALF_W / 4;
    if (i >= total) return;
    const size_t n = i >> 8;
    const size_t c = i & 255;
    const size_t off = n * 512 + 256 + c;
    const float4 v = src[off];
    const __nv_bfloat162 lo = __floats2bfloat162_rn(v.x, v.y);
    const __nv_bfloat162 hi = __floats2bfloat162_rn(v.z, v.w);
    uint2 o;
    o.x = *reinterpret_cast<const uint32_t*>(&lo);
    o.y = *reinterpret_cast<const uint32_t*>(&hi);
    dst[off] = o;
}

__device__ __forceinline__ float sigmoidf_(float x) {
    return 1.f / (1.f + expf(-x));
}

__global__ void build_x_kernel(const float* __restrict__ inputs,
                               const float* __restrict__ states,
                               float* __restrict__ X)
{
    int idx = blockIdx.x * blockDim.x + threadIdx.x;
    if (idx >= NN * BD) return;
    const int n = idx >> 11;
    const int r = idx & 2047;
    float v;
    if (r < HALF_W) {
        const int b = r >> 6, d = r & 63;
        v = inputs[((size_t)b * NN + n) * DHH + d];
    } else {
        const int r2 = r - HALF_W;
        const int b = r2 >> 6, d = r2 & 63;
        v = states[((size_t)b * NN + n) * DHH + d];
    }
    X[idx] = v;
}

__global__ void gate_kernel(const float* __restrict__ states,
                            const float* __restrict__ PRE,
                            float* __restrict__ X,
                            float* __restrict__ U)
{
    int idx = blockIdx.x * blockDim.x + threadIdx.x;
    if (idx >= NN * NB * DHH) return;
    const int n = idx / (NB * DHH);
    const int r0 = idx - n * (NB * DHH);
    const int b = r0 >> 6;
    const int d = r0 & 63;
    const size_t prow = (size_t)(n * NB + b) * DCAT;
    const float rr = sigmoidf_(PRE[prow + d]);
    const float uu = sigmoidf_(PRE[prow + DHH + d]);
    U[idx] = uu;
    const float st = states[((size_t)b * NN + n) * DHH + d];
    X[(size_t)n * BD + HALF_W + (size_t)b * DHH + d] = rr * st;
}

__global__ void final_kernel(const float* __restrict__ states,
                             const float* __restrict__ PREC,
                             const float* __restrict__ U,
                             float* __restrict__ out,
                             int out_size)
{
    int idx = blockIdx.x * blockDim.x + threadIdx.x;
    if (idx >= NN * NB * DHH) return;
    const int n = idx / (NB * DHH);
    const int r0 = idx - n * (NB * DHH);
    const int b = r0 >> 6;
    const int d = r0 & 63;
    const float uu = U[idx];
    const float cc = tanhf(PREC[(size_t)(n * NB + b) * DHH + d]);
    const float st = states[((size_t)b * NN + n) * DHH + d];
    const float ns = uu * st + (1.f - uu) * cc;
    const size_t o = ((size_t)b * NN + n) * DHH + d;
    out[o] = ns;
    const size_t total = (size_t)NB * NN * DHH;
    if ((size_t)out_size >= 2 * total) out[total + o] = ns;
}

// ============================ launch ============================

extern "C" void kernel_launch(void* const* d_in, const int* in_sizes, int n_in,
                              void* d_out, int out_size)
{
    const float* inputs   = (const float*)d_in[0];
    const float* states   = (const float*)d_in[1];
    const float* supports = (const float*)d_in[2];
    const float* W_ru     = (const float*)d_in[3];
    const float* b_ru     = (const float*)d_in[4];
    const float* W_c      = (const float*)d_in[5];
    const float* b_c      = (const float*)d_in[6];
    float* out = (float*)d_out;

    float *pX, *pT1a, *pT2a, *pT1c, *pT2c, *pPRE, *pU;
    __nv_bfloat16 *pSb, *pXb, *pT1b;
    cudaGetSymbolAddress((void**)&pX,   g_X);
    cudaGetSymbolAddress((void**)&pT1a, g_T1a);
    cudaGetSymbolAddress((void**)&pT2a, g_T2a);
    cudaGetSymbolAddress((void**)&pT1c, g_T1c);
    cudaGetSymbolAddress((void**)&pT2c, g_T2c);
    cudaGetSymbolAddress((void**)&pPRE, g_PRE);
    cudaGetSymbolAddress((void**)&pU,   g_U);
    cudaGetSymbolAddress((void**)&pSb,  g_Sb);
    cudaGetSymbolAddress((void**)&pXb,  g_Xb);
    cudaGetSymbolAddress((void**)&pT1b, g_T1b);

    cudaFuncSetAttribute(hgemm_kernel,
                         cudaFuncAttributeMaxDynamicSharedMemorySize, HG_SMEM);

    const __nv_bfloat16* S0b = pSb;
    const __nv_bfloat16* S1b = pSb + (size_t)NN * NN;

    const dim3 blk(256);
    const dim3 gFull(BD / 128, NN / 128);
    const dim3 gHalf(HALF_W / 128, NN / 128);
    const dim3 gProj(1, (NN * NB) / TBM);

    const size_t nS4 = (size_t)2 * NN * NN / 4;
    const size_t nX4 = (size_t)NN * BD / 4;
    const size_t nH4 = (size_t)NN * HALF_W / 4;
    const int gS = (int)((nS4 + 255) / 256);
    const int gX = (int)((nX4 + 255) / 256);
    const int gH = (int)((nH4 + 255) / 256);

    // ---- prep ----
    build_x_kernel<<<(NN * BD + 255) / 256, blk>>>(inputs, states, pX);
    f2bf_kernel<<<gS, blk>>>((const float4*)supports, (uint2*)pSb, nS4);
    f2bf_kernel<<<gX, blk>>>((const float4*)pX, (uint2*)pXb, nX4);

    // ---------- phase 1 hops (full width), bf16 mirrors fused ----------
    hgemm_kernel<<<gFull, blk, HG_SMEM>>>(S0b, NN, pXb, BD, pT1a, BD,
                                          (const float*)0, 0, pT1b, 1.f, 0.f, NN);
    hgemm_kernel<<<gFull, blk, HG_SMEM>>>(S0b, NN, pT1b, BD, pT2a, BD,
                                          pX, BD, (__nv_bfloat16*)0, 2.f, -1.f, NN);
    hgemm_kernel<<<gFull, blk, HG_SMEM>>>(S1b, NN, pXb, BD, pT1c, BD,
                                          (const float*)0, 0, pT1b, 1.f, 0.f, NN);
    hgemm_kernel<<<gFull, blk, HG_SMEM>>>(S1b, NN, pT1b, BD, pT2c, BD,
                                          pX, BD, (__nv_bfloat16*)0, 2.f, -1.f, NN);

    // ---------- fused ru projection (K=640) ----------
    tf32_proj5_kernel<<<gProj, blk>>>(pX, pT1a, pT2a, pT1c, pT2c,
                                      W_ru, 2 * DHH, pPRE, b_ru);

    // ---------- gates ----------
    gate_kernel<<<(NN * NB * DHH + 255) / 256, blk>>>(states, pPRE, pX, pU);
    f2bf_st_kernel<<<gH, blk>>>((const float4*)pX, (uint2*)pXb);

    // ---------- phase 2 hops (st halves only, width 1024) ----------
    hgemm_kernel<<<gHalf, blk, HG_SMEM>>>(S0b, NN, pXb + HALF_W, BD, pT1a + HALF_W, BD,
                                          (const float*)0, 0, pT1b + HALF_W, 1.f, 0.f, NN);
    hgemm_kernel<<<gHalf, blk, HG_SMEM>>>(S0b, NN, pT1b + HALF_W, BD, pT2a + HALF_W, BD,
                                          pX + HALF_W, BD, (__nv_bfloat16*)0, 2.f, -1.f, NN);
    hgemm_kernel<<<gHalf, blk, HG_SMEM>>>(S1b, NN, pXb + HALF_W, BD, pT1c + HALF_W, BD,
                                          (const float*)0, 0, pT1b + HALF_W, 1.f, 0.f, NN);
    hgemm_kernel<<<gHalf, blk, HG_SMEM>>>(S1b, NN, pT1b + HALF_W, BD, pT2c + HALF_W, BD,
                                          pX + HALF_W, BD, (__nv_bfloat16*)0, 2.f, -1.f, NN);

    // ---------- fused c projection (K=640, Nc=64) ----------
    tf32_proj5_kernel<<<gProj, blk>>>(pX, pT1a, pT2a, pT1c, pT2c,
                                      W_c, DHH, pPRE, b_c);

    // ---------- final state ----------
    final_kernel<<<(NN * NB * DHH + 255) / 256, blk>>>(states, pPRE, pU, out, out_size);
}